// round 1
// baseline (speedup 1.0000x reference)
#include <cuda_runtime.h>

// ============================================================================
// EnasController: fully-sequential ENAS RNN controller sampler.
// One block / 256 threads runs the whole 12-layer program:
//   - 2-layer LSTM (HID=64, gates 4H=256 -> one thread per gate row)
//   - branch sampling via JAX threefry gumbel-argmax (replicated bit-exact)
//   - skip-attention + skip sampling + entropy/KL accumulation
// All recurrent state lives in shared memory; weights stream from L1/L2.
//
// RNG: JAX threefry2x32. JAX >= 0.4.36 defaults jax_threefry_partitionable=True:
//   split(key,n)[i]    = threefry(key, (0, i))            (both 32-bit outputs)
//   random_bits32[i]   = out0 ^ out1 of threefry(key,(0,i))
// Legacy (partitionable=False) scheme kept under the macro for fallback:
//   bits(n even): pair p -> threefry(key,(p, p+n/2)); bits=[a0..,b0..]
// ============================================================================

#define JAX_PARTITIONABLE 1

#define N_LAYERS 12
#define NB 6
#define HID 64

__device__ __forceinline__ unsigned rotl32(unsigned x, int r) {
    return (x << r) | (x >> (32 - r));
}

__device__ __forceinline__ void tf2x32(unsigned k0, unsigned k1,
                                       unsigned x0, unsigned x1,
                                       unsigned &o0, unsigned &o1) {
    const unsigned ks2 = k0 ^ k1 ^ 0x1BD11BDAu;
    x0 += k0; x1 += k1;
    x0+=x1; x1=rotl32(x1,13); x1^=x0;
    x0+=x1; x1=rotl32(x1,15); x1^=x0;
    x0+=x1; x1=rotl32(x1,26); x1^=x0;
    x0+=x1; x1=rotl32(x1, 6); x1^=x0;
    x0+=k1; x1+=ks2+1u;
    x0+=x1; x1=rotl32(x1,17); x1^=x0;
    x0+=x1; x1=rotl32(x1,29); x1^=x0;
    x0+=x1; x1=rotl32(x1,16); x1^=x0;
    x0+=x1; x1=rotl32(x1,24); x1^=x0;
    x0+=ks2; x1+=k0+2u;
    x0+=x1; x1=rotl32(x1,13); x1^=x0;
    x0+=x1; x1=rotl32(x1,15); x1^=x0;
    x0+=x1; x1=rotl32(x1,26); x1^=x0;
    x0+=x1; x1=rotl32(x1, 6); x1^=x0;
    x0+=k0; x1+=k1+3u;
    x0+=x1; x1=rotl32(x1,17); x1^=x0;
    x0+=x1; x1=rotl32(x1,29); x1^=x0;
    x0+=x1; x1=rotl32(x1,16); x1^=x0;
    x0+=x1; x1=rotl32(x1,24); x1^=x0;
    x0+=k1; x1+=ks2+4u;
    x0+=x1; x1=rotl32(x1,13); x1^=x0;
    x0+=x1; x1=rotl32(x1,15); x1^=x0;
    x0+=x1; x1=rotl32(x1,26); x1^=x0;
    x0+=x1; x1=rotl32(x1, 6); x1^=x0;
    x0+=ks2; x1+=k0+5u;
    o0 = x0; o1 = x1;
}

// 32-bit random draw at flat index `idx` within a draw of total (even) size `n`.
__device__ __forceinline__ unsigned rbits32(unsigned k0, unsigned k1, int idx, int n) {
#if JAX_PARTITIONABLE
    unsigned o0, o1;
    tf2x32(k0, k1, 0u, (unsigned)idx, o0, o1);
    (void)n;
    return o0 ^ o1;
#else
    const int half = n >> 1;
    unsigned o0, o1;
    if (idx < half) { tf2x32(k0, k1, (unsigned)idx, (unsigned)(idx + half), o0, o1); return o0; }
    else            { tf2x32(k0, k1, (unsigned)(idx - half), (unsigned)idx, o0, o1); return o1; }
#endif
}

__device__ __forceinline__ float gumbel_from_bits(unsigned bits) {
    // jax.random.uniform(minval=tiny, maxval=1):  f in [0,1), u = max(tiny, f*(1-tiny)+tiny)
    const float TINY = 1.17549435e-38f;
    float f = __uint_as_float(0x3f800000u | (bits >> 9)) - 1.0f;
    float u = fmaxf(TINY, f + TINY);   // (1-tiny) rounds to 1.0f in fp32
    return -logf(-logf(u));
}

__device__ __forceinline__ float dot64(const float* __restrict__ w, const float* xs_) {
    const float4* w4 = (const float4*)w;
    const float4* x4 = (const float4*)xs_;
    float a0 = 0.f, a1 = 0.f, a2 = 0.f, a3 = 0.f;
#pragma unroll
    for (int k = 0; k < 16; k++) {
        float4 wv = __ldg(&w4[k]);
        float4 xv = x4[k];
        a0 = fmaf(wv.x, xv.x, a0);
        a1 = fmaf(wv.y, xv.y, a1);
        a2 = fmaf(wv.z, xv.z, a2);
        a3 = fmaf(wv.w, xv.w, a3);
    }
    return (a0 + a1) + (a2 + a3);
}

__device__ __forceinline__ float sigmoidf_(float x) {
    return 1.0f / (1.0f + expf(-x));
}

// One LSTM cell step. 256 threads compute gate rows; threads <64 update h,c.
__device__ __forceinline__ void lstm_cell(const float* __restrict__ wi,
                                          const float* __restrict__ wh,
                                          const float* __restrict__ bi,
                                          const float* __restrict__ bh,
                                          const float* x, float* h, float* c,
                                          float* gbuf, int t) {
    float acc = __ldg(&bi[t]) + __ldg(&bh[t]) + dot64(wi + t * HID, x) + dot64(wh + t * HID, h);
    gbuf[t] = acc;
    __syncthreads();
    if (t < HID) {
        float gi = gbuf[t];
        float gf = gbuf[HID + t];
        float gg = gbuf[2 * HID + t];
        float go = gbuf[3 * HID + t];
        float cn = sigmoidf_(gf) * c[t] + sigmoidf_(gi) * tanhf(gg);
        c[t] = cn;
        h[t] = sigmoidf_(go) * tanhf(cn);
    }
    __syncthreads();
}

__global__ __launch_bounds__(256, 1)
void enas_controller_kernel(const float* __restrict__ g_emb,
                            const float* __restrict__ w_emb,
                            const float* __restrict__ w_soft,
                            const float* __restrict__ w_attn2,
                            const float* __restrict__ v_attn,
                            const float* __restrict__ w_ih0,
                            const float* __restrict__ w_hh0,
                            const float* __restrict__ b_ih0,
                            const float* __restrict__ b_hh0,
                            const float* __restrict__ w_ih1,
                            const float* __restrict__ w_hh1,
                            const float* __restrict__ b_ih1,
                            const float* __restrict__ b_hh1,
                            const int* __restrict__ seed_p,
                            float* __restrict__ out3) {
    __shared__ __align__(16) float xs[HID];
    __shared__ __align__(16) float h0v[HID], c0v[HID], h1v[HID], c1v[HID];
    __shared__ __align__(16) float gbuf[4 * HID];
    __shared__ __align__(16) float anchors[N_LAYERS][HID];
    __shared__ __align__(16) float aw1[N_LAYERS][HID];
    __shared__ __align__(16) float w2out[HID];
    __shared__ float qv[N_LAYERS];
    __shared__ float row_lp[N_LAYERS], row_ent[N_LAYERS], row_kl[N_LAYERS];
    __shared__ int   skips_s[N_LAYERS];
    __shared__ float logits6[NB];
    __shared__ float gum6[NB];
    __shared__ unsigned kb0s, kb1s, ks0s, ks1s;
    __shared__ int   out_id_s;
    __shared__ float den_s;

    const int t = threadIdx.x;

    if (t < HID) {
        xs[t]  = g_emb[t];   // inputs = g_emb[0]
        h0v[t] = 0.f; c0v[t] = 0.f; h1v[t] = 0.f; c1v[t] = 0.f;
    }

    // jax.random.key(seed): data = (seed>>32, seed&0xffffffff) -> (0, seed) for int32
    unsigned key0 = 0u, key1 = 0u;
    if (t == 0) key1 = (unsigned)seed_p[0];

    float lp_sum = 0.f, ent_sum = 0.f, kl_sum = 0.f;  // live only in thread 0

    __syncthreads();

    for (int lid = 0; lid < N_LAYERS; ++lid) {
        // ---- key, kb, ks = jax.random.split(key, 3) ----
        if (t == 0) {
#if JAX_PARTITIONABLE
            unsigned a0, a1, b0, b1, c0_, c1_;
            tf2x32(key0, key1, 0u, 0u, a0, a1);
            tf2x32(key0, key1, 0u, 1u, b0, b1);
            tf2x32(key0, key1, 0u, 2u, c0_, c1_);
            key0 = a0; key1 = a1;
            kb0s = b0; kb1s = b1;
            ks0s = c0_; ks1s = c1_;
#else
            // bits = [a0,a1,a2,b0,b1,b2] from pairs (0,3),(1,4),(2,5); reshape (3,2)
            unsigned a0, a1, a2, b0, b1, b2;
            tf2x32(key0, key1, 0u, 3u, a0, b0);
            tf2x32(key0, key1, 1u, 4u, a1, b1);
            tf2x32(key0, key1, 2u, 5u, a2, b2);
            key0 = a0; key1 = a1;
            kb0s = a2; kb1s = b0;
            ks0s = b1; ks1s = b2;
#endif
        }

        // ---- out, st = lstm(inputs, st)  (first call) ----
        lstm_cell(w_ih0, w_hh0, b_ih0, b_hh0, xs,  h0v, c0v, gbuf, t);
        lstm_cell(w_ih1, w_hh1, b_ih1, b_hh1, h0v, h1v, c1v, gbuf, t);
        // out == h1v

        // ---- logit = w_soft @ out ; gumbel(kb, (6,)) in a second warp ----
        if (t < NB) logits6[t] = dot64(w_soft + t * HID, h1v);
#if JAX_PARTITIONABLE
        if (t >= 32 && t < 32 + NB)
            gum6[t - 32] = gumbel_from_bits(rbits32(kb0s, kb1s, t - 32, NB));
#else
        if (t >= 32 && t < 32 + 3) {
            unsigned o0, o1;
            tf2x32(kb0s, kb1s, (unsigned)(t - 32), (unsigned)(t - 32 + 3), o0, o1);
            gum6[t - 32]     = gumbel_from_bits(o0);
            gum6[t - 32 + 3] = gumbel_from_bits(o1);
        }
#endif
        __syncthreads();

        // ---- categorical + log_softmax + entropy (serial, tiny) ----
        if (t == 0) {
            float m = logits6[0];
#pragma unroll
            for (int j = 1; j < NB; j++) m = fmaxf(m, logits6[j]);
            float s = 0.f;
#pragma unroll
            for (int j = 0; j < NB; j++) s += expf(logits6[j] - m);
            float lse = logf(s);
            int best = 0;
            float bz = logits6[0] + gum6[0];
#pragma unroll
            for (int j = 1; j < NB; j++) {
                float z = logits6[j] + gum6[j];
                if (z > bz) { bz = z; best = j; }   // argmax, first-max on tie
            }
            out_id_s = best;
            lp_sum += (logits6[best] - m) - lse;
            float ent = 0.f;
#pragma unroll
            for (int j = 0; j < NB; j++) {
                float lp = (logits6[j] - m) - lse;
                ent -= expf(lp) * lp;
            }
            ent_sum += ent;
        }
        __syncthreads();

        // ---- inputs = w_emb[out_id] ----
        if (t < HID) xs[t] = w_emb[out_id_s * HID + t];
        __syncthreads();

        // ---- out, st = lstm(inputs, st)  (second call) ----
        lstm_cell(w_ih0, w_hh0, b_ih0, b_hh0, xs,  h0v, c0v, gbuf, t);
        lstm_cell(w_ih1, w_hh1, b_ih1, b_hh1, h0v, h1v, c1v, gbuf, t);

        // ---- anchors / anchors_w1 (out @ w_attn2.T used for both q and the append) ----
        if (t < HID) {
            float v = dot64(w_attn2 + t * HID, h1v);
            w2out[t] = v;
            aw1[lid][t] = v;
            anchors[lid][t] = h1v[t];
        }
        __syncthreads();

        if (lid > 0) {
            // q_i = tanh(aw1[i] + w2out) . v_attn
            if (t < lid) {
                float acc = 0.f;
                for (int j = 0; j < HID; j++)
                    acc += tanhf(aw1[t][j] + w2out[j]) * __ldg(&v_attn[j]);
                qv[t] = acc;
            }
            __syncthreads();

            // per-row skip sampling + stats (gumbel shape (lid,2), flat index 2i+c)
            if (t < lid) {
                float q  = qv[t];
                float l0 = 1.5f * tanhf(q);
                float l1 = 1.5f * tanhf(-q);
                unsigned bb0 = rbits32(ks0s, ks1s, 2 * t,     2 * lid);
                unsigned bb1 = rbits32(ks0s, ks1s, 2 * t + 1, 2 * lid);
                float g0 = gumbel_from_bits(bb0);
                float g1 = gumbel_from_bits(bb1);
                float m   = fmaxf(l0, l1);
                float lsr = logf(expf(l0 - m) + expf(l1 - m));
                float lp0 = (l0 - m) - lsr;
                float lp1 = (l1 - m) - lsr;
                int sk = (l1 + g1 > l0 + g0) ? 1 : 0;  // argmax, first-max on tie
                skips_s[t] = sk;
                row_lp[t]  = sk ? lp1 : lp0;
                row_ent[t] = -(expf(lp0) * lp0 + expf(lp1) * lp1);
                float s0 = sigmoidf_(l0);
                float s1 = sigmoidf_(l1);
                row_kl[t] = s0 * logf(s0 / 0.8f) + s1 * logf(s1 / 0.8f);
            }
            __syncthreads();

            if (t == 0) {
                int sc = 0;
                for (int i = 0; i < lid; i++) {
                    lp_sum  += row_lp[i];
                    ent_sum += row_ent[i];
                    kl_sum  += row_kl[i];
                    sc += skips_s[i];
                }
                den_s = 1.0f + (float)sc;
            }
            __syncthreads();

            // inputs = (skips @ anchors) / (1 + sc)
            if (t < HID) {
                float acc = 0.f;
                for (int i = 0; i < lid; i++)
                    acc += skips_s[i] ? anchors[i][t] : 0.0f;
                xs[t] = acc / den_s;
            }
            __syncthreads();
        } else {
            if (t < HID) xs[t] = g_emb[t];
            __syncthreads();
        }
    }

    if (t == 0) {
        out3[0] = lp_sum;
        out3[1] = ent_sum;
        out3[2] = kl_sum;
    }
}

extern "C" void kernel_launch(void* const* d_in, const int* in_sizes, int n_in,
                              void* d_out, int out_size) {
    const float* g_emb   = (const float*)d_in[0];
    const float* w_emb   = (const float*)d_in[1];
    const float* w_soft  = (const float*)d_in[2];
    const float* w_attn2 = (const float*)d_in[3];
    const float* v_attn  = (const float*)d_in[4];
    const float* w_ih0   = (const float*)d_in[5];
    const float* w_hh0   = (const float*)d_in[6];
    const float* b_ih0   = (const float*)d_in[7];
    const float* b_hh0   = (const float*)d_in[8];
    const float* w_ih1   = (const float*)d_in[9];
    const float* w_hh1   = (const float*)d_in[10];
    const float* b_ih1   = (const float*)d_in[11];
    const float* b_ih1b  = (const float*)d_in[12];  // b_hh1
    const int*   seed    = (const int*)d_in[13];

    enas_controller_kernel<<<1, 256>>>(g_emb, w_emb, w_soft, w_attn2, v_attn,
                                       w_ih0, w_hh0, b_ih0, b_hh0,
                                       w_ih1, w_hh1, b_ih1, b_ih1b,
                                       seed, (float*)d_out);
}

// round 2
// speedup vs baseline: 4.3514x; 4.3514x over previous
#include <cuda_runtime.h>

// ============================================================================
// EnasController R2: smem/register-resident weights, MUFU transcendentals,
// fully precomputed RNG (all 204 gumbels hoisted out of the serial loop),
// warp-parallel skip attention. One persistent block, 256 threads.
// ============================================================================

#define N_LAYERS 12
#define NB 6
#define HID 64
#define PAD 68   // padded row stride (floats) -> conflict-free LDS.128

// ---- shared memory layout (float offsets) ----
#define OF_WIH0   0                       // 256*68
#define OF_WIH1   (OF_WIH0 + 256*PAD)     // 256*68
#define OF_WAT2   (OF_WIH1 + 256*PAD)     // 64*68
#define OF_BSUM0  (OF_WAT2 + 64*PAD)      // 256
#define OF_BSUM1  (OF_BSUM0 + 256)        // 256
#define OF_WSOFT  (OF_BSUM1 + 256)        // 6*64
#define OF_VATTN  (OF_WSOFT + NB*HID)     // 64
#define OF_XS     (OF_VATTN + 64)         // 64
#define OF_H0     (OF_XS + 64)
#define OF_C0     (OF_H0 + 64)
#define OF_H1     (OF_C0 + 64)
#define OF_C1     (OF_H1 + 64)
#define OF_GBUF   (OF_C1 + 64)            // 256
#define OF_ANCH   (OF_GBUF + 256)         // 12*64
#define OF_AW1    (OF_ANCH + N_LAYERS*64) // 12*64
#define OF_W2OUT  (OF_AW1 + N_LAYERS*64)  // 64
#define OF_QV     (OF_W2OUT + 64)         // 12
#define OF_RLP    (OF_QV + 12)            // 12
#define OF_RENT   (OF_RLP + 12)
#define OF_RKL    (OF_RENT + 12)
#define OF_LOG6   (OF_RKL + 12)           // 8
#define OF_GUMB   (OF_LOG6 + 8)           // 12*6
#define OF_GUMS   (OF_GUMB + N_LAYERS*NB) // 132
#define OF_DEN    (OF_GUMS + 132)         // 1
#define OF_IREG   (OF_DEN + 3)            // int region (aligned)
// int region (as uint): skips[12], out_id[1], lkey[12*2], kb[12*2], ks[12*2]
#define IO_SKIPS  0
#define IO_OUTID  12
#define IO_LKEY   13
#define IO_KB     (IO_LKEY + 24)
#define IO_KS     (IO_KB + 24)
#define SMEM_FLOATS (OF_IREG + 96)
#define SMEM_BYTES  (SMEM_FLOATS * 4)

__device__ __forceinline__ unsigned rotl32(unsigned x, int r) {
    return (x << r) | (x >> (32 - r));
}

__device__ __forceinline__ void tf2x32(unsigned k0, unsigned k1,
                                       unsigned x0, unsigned x1,
                                       unsigned &o0, unsigned &o1) {
    const unsigned ks2 = k0 ^ k1 ^ 0x1BD11BDAu;
    x0 += k0; x1 += k1;
    x0+=x1; x1=rotl32(x1,13); x1^=x0;
    x0+=x1; x1=rotl32(x1,15); x1^=x0;
    x0+=x1; x1=rotl32(x1,26); x1^=x0;
    x0+=x1; x1=rotl32(x1, 6); x1^=x0;
    x0+=k1; x1+=ks2+1u;
    x0+=x1; x1=rotl32(x1,17); x1^=x0;
    x0+=x1; x1=rotl32(x1,29); x1^=x0;
    x0+=x1; x1=rotl32(x1,16); x1^=x0;
    x0+=x1; x1=rotl32(x1,24); x1^=x0;
    x0+=ks2; x1+=k0+2u;
    x0+=x1; x1=rotl32(x1,13); x1^=x0;
    x0+=x1; x1=rotl32(x1,15); x1^=x0;
    x0+=x1; x1=rotl32(x1,26); x1^=x0;
    x0+=x1; x1=rotl32(x1, 6); x1^=x0;
    x0+=k0; x1+=k1+3u;
    x0+=x1; x1=rotl32(x1,17); x1^=x0;
    x0+=x1; x1=rotl32(x1,29); x1^=x0;
    x0+=x1; x1=rotl32(x1,16); x1^=x0;
    x0+=x1; x1=rotl32(x1,24); x1^=x0;
    x0+=k1; x1+=ks2+4u;
    x0+=x1; x1=rotl32(x1,13); x1^=x0;
    x0+=x1; x1=rotl32(x1,15); x1^=x0;
    x0+=x1; x1=rotl32(x1,26); x1^=x0;
    x0+=x1; x1=rotl32(x1, 6); x1^=x0;
    x0+=ks2; x1+=k0+5u;
    o0 = x0; o1 = x1;
}

// JAX partitionable random_bits: out0 ^ out1 of threefry(key, (0, idx))
__device__ __forceinline__ unsigned rbits32(unsigned k0, unsigned k1, int idx) {
    unsigned o0, o1;
    tf2x32(k0, k1, 0u, (unsigned)idx, o0, o1);
    return o0 ^ o1;
}

__device__ __forceinline__ float gumbel_from_bits(unsigned bits) {
    const float TINY = 1.17549435e-38f;
    float f = __uint_as_float(0x3f800000u | (bits >> 9)) - 1.0f;
    float u = fmaxf(TINY, f + TINY);
    return -logf(-logf(u));   // accurate logf: protects argmax agreement
}

// MUFU-based sigmoid/tanh (err ~1e-7, vs tanh.approx's 1e-5)
__device__ __forceinline__ float fsig(float x) {
    return __fdividef(1.0f, 1.0f + __expf(-x));
}
__device__ __forceinline__ float ftanh(float x) {
    float ax = fabsf(x);
    float e  = __expf(-2.0f * ax);
    float r  = __fdividef(1.0f - e, 1.0f + e);
    return copysignf(r, x);
}

// One LSTM cell. wih_row: this thread's padded smem row; wreg: this thread's
// w_hh row in registers. 256 threads = gate rows; t<64 do the state update.
__device__ __forceinline__ void cell(const float* __restrict__ wih_row,
                                     const float* __restrict__ wreg,
                                     float bsum,
                                     const float* __restrict__ x,
                                     float* __restrict__ h,
                                     float* __restrict__ c,
                                     float* __restrict__ gbuf, int t) {
    const float4* x4 = (const float4*)x;
    const float4* w4 = (const float4*)wih_row;
    const float4* h4 = (const float4*)h;
    float a0 = bsum, a1 = 0.f, a2 = 0.f, a3 = 0.f;
#pragma unroll
    for (int k = 0; k < 16; k++) {
        float4 xv = x4[k];
        float4 wv = w4[k];
        a0 = fmaf(wv.x, xv.x, a0);
        a1 = fmaf(wv.y, xv.y, a1);
        a2 = fmaf(wv.z, xv.z, a2);
        a3 = fmaf(wv.w, xv.w, a3);
    }
#pragma unroll
    for (int k = 0; k < 16; k++) {
        float4 hv = h4[k];
        a0 = fmaf(wreg[4*k+0], hv.x, a0);
        a1 = fmaf(wreg[4*k+1], hv.y, a1);
        a2 = fmaf(wreg[4*k+2], hv.z, a2);
        a3 = fmaf(wreg[4*k+3], hv.w, a3);
    }
    gbuf[t] = (a0 + a1) + (a2 + a3);
    __syncthreads();
    if (t < HID) {
        float gi = gbuf[t];
        float gf = gbuf[HID + t];
        float gg = gbuf[2*HID + t];
        float go = gbuf[3*HID + t];
        float cn = fsig(gf) * c[t] + fsig(gi) * ftanh(gg);
        c[t] = cn;
        h[t] = fsig(go) * ftanh(cn);
    }
    __syncthreads();
}

__global__ __launch_bounds__(256, 1)
void enas_controller_kernel(const float* __restrict__ g_emb,
                            const float* __restrict__ w_emb,
                            const float* __restrict__ w_soft,
                            const float* __restrict__ w_attn2,
                            const float* __restrict__ v_attn,
                            const float* __restrict__ w_ih0,
                            const float* __restrict__ w_hh0,
                            const float* __restrict__ b_ih0,
                            const float* __restrict__ b_hh0,
                            const float* __restrict__ w_ih1,
                            const float* __restrict__ w_hh1,
                            const float* __restrict__ b_ih1,
                            const float* __restrict__ b_hh1,
                            const int* __restrict__ seed_p,
                            float* __restrict__ out3) {
    extern __shared__ __align__(16) float S[];
    unsigned* SI = (unsigned*)&S[OF_IREG];
    const int t = threadIdx.x;

    // ---- stage w_ih0 / w_ih1 into padded smem (coalesced) ----
    {
        const float4* g0 = (const float4*)w_ih0;
        const float4* g1 = (const float4*)w_ih1;
        for (int idx = t; idx < 256*16; idx += 256) {
            int row = idx >> 4, col = idx & 15;
            *(float4*)&S[OF_WIH0 + row*PAD + col*4] = __ldg(&g0[idx]);
            *(float4*)&S[OF_WIH1 + row*PAD + col*4] = __ldg(&g1[idx]);
        }
        const float4* ga = (const float4*)w_attn2;
        for (int idx = t; idx < 64*16; idx += 256) {
            int row = idx >> 4, col = idx & 15;
            *(float4*)&S[OF_WAT2 + row*PAD + col*4] = __ldg(&ga[idx]);
        }
        const float4* gs = (const float4*)w_soft;
        if (t < NB*16) *(float4*)&S[OF_WSOFT + t*4] = __ldg(&gs[t]);
        S[OF_BSUM0 + t] = __ldg(&b_ih0[t]) + __ldg(&b_hh0[t]);
        S[OF_BSUM1 + t] = __ldg(&b_ih1[t]) + __ldg(&b_hh1[t]);
        if (t < HID) {
            S[OF_VATTN + t] = __ldg(&v_attn[t]);
            S[OF_XS + t] = g_emb[t];
            S[OF_H0 + t] = 0.f; S[OF_C0 + t] = 0.f;
            S[OF_H1 + t] = 0.f; S[OF_C1 + t] = 0.f;
        }
    }

    // ---- w_hh rows into registers ----
    float wr0[64], wr1[64];
    {
        const float4* p0 = (const float4*)(w_hh0 + t*HID);
        const float4* p1 = (const float4*)(w_hh1 + t*HID);
#pragma unroll
        for (int k = 0; k < 16; k++) {
            float4 v0 = __ldg(&p0[k]);
            float4 v1 = __ldg(&p1[k]);
            wr0[4*k+0] = v0.x; wr0[4*k+1] = v0.y; wr0[4*k+2] = v0.z; wr0[4*k+3] = v0.w;
            wr1[4*k+0] = v1.x; wr1[4*k+1] = v1.y; wr1[4*k+2] = v1.z; wr1[4*k+3] = v1.w;
        }
    }

    // ---- RNG precompute: key chain (serial, data-independent), then all
    //      per-layer kb/ks keys and all 204 gumbels in parallel ----
    if (t == 0) {
        unsigned k0 = 0u, k1 = (unsigned)seed_p[0];
        for (int l = 0; l < N_LAYERS; l++) {
            SI[IO_LKEY + 2*l]     = k0;
            SI[IO_LKEY + 2*l + 1] = k1;
            unsigned a0, a1;
            tf2x32(k0, k1, 0u, 0u, a0, a1);
            k0 = a0; k1 = a1;
        }
    }
    __syncthreads();
    if (t < 24) {
        int l = t >> 1, which = t & 1;  // which=0 -> kb (x1=1), which=1 -> ks (x1=2)
        unsigned o0, o1;
        tf2x32(SI[IO_LKEY + 2*l], SI[IO_LKEY + 2*l + 1], 0u, (unsigned)(1 + which), o0, o1);
        int base = which ? IO_KS : IO_KB;
        SI[base + 2*l] = o0; SI[base + 2*l + 1] = o1;
    }
    __syncthreads();
    if (t < 72) {
        int l = t / NB, j = t % NB;
        S[OF_GUMB + l*NB + j] =
            gumbel_from_bits(rbits32(SI[IO_KB + 2*l], SI[IO_KB + 2*l + 1], j));
    } else if (t < 72 + 132) {
        int f = t - 72;               // layer l occupies [l*(l-1), l*(l+1))
        int l = 1;
        while (f >= l*(l+1)) l++;
        int j = f - l*(l-1);
        S[OF_GUMS + f] =
            gumbel_from_bits(rbits32(SI[IO_KS + 2*l], SI[IO_KS + 2*l + 1], j));
    }
    __syncthreads();

    float lp_sum = 0.f, ent_sum = 0.f, kl_sum = 0.f;   // thread 0 only
    const float* my_wih0 = &S[OF_WIH0 + t*PAD];
    const float* my_wih1 = &S[OF_WIH1 + t*PAD];
    const float  b0 = S[OF_BSUM0 + t];
    const float  b1 = S[OF_BSUM1 + t];

#pragma unroll 1
    for (int lid = 0; lid < N_LAYERS; ++lid) {
        // ---- lstm #1 ----
        cell(my_wih0, wr0, b0, &S[OF_XS], &S[OF_H0], &S[OF_C0], &S[OF_GBUF], t);
        cell(my_wih1, wr1, b1, &S[OF_H0], &S[OF_H1], &S[OF_C1], &S[OF_GBUF], t);

        // ---- logits ----
        if (t < NB) {
            const float4* w4 = (const float4*)&S[OF_WSOFT + t*HID];
            const float4* h4 = (const float4*)&S[OF_H1];
            float a0 = 0.f, a1 = 0.f, a2 = 0.f, a3 = 0.f;
#pragma unroll
            for (int k = 0; k < 16; k++) {
                float4 wv = w4[k]; float4 hv = h4[k];
                a0 = fmaf(wv.x, hv.x, a0);
                a1 = fmaf(wv.y, hv.y, a1);
                a2 = fmaf(wv.z, hv.z, a2);
                a3 = fmaf(wv.w, hv.w, a3);
            }
            S[OF_LOG6 + t] = (a0 + a1) + (a2 + a3);
        }
        __syncthreads();

        // ---- branch sample + stats (tiny; thread 0) ----
        if (t == 0) {
            float l[NB];
#pragma unroll
            for (int j = 0; j < NB; j++) l[j] = S[OF_LOG6 + j];
            float m = l[0];
#pragma unroll
            for (int j = 1; j < NB; j++) m = fmaxf(m, l[j]);
            float s = 0.f;
#pragma unroll
            for (int j = 0; j < NB; j++) s += __expf(l[j] - m);
            float lse = __logf(s);
            int best = 0;
            float bz = l[0] + S[OF_GUMB + lid*NB];
#pragma unroll
            for (int j = 1; j < NB; j++) {
                float z = l[j] + S[OF_GUMB + lid*NB + j];
                if (z > bz) { bz = z; best = j; }
            }
            SI[IO_OUTID] = (unsigned)best;
            lp_sum += (l[best] - m) - lse;
            float ent = 0.f;
#pragma unroll
            for (int j = 0; j < NB; j++) {
                float lp = (l[j] - m) - lse;
                ent -= __expf(lp) * lp;
            }
            ent_sum += ent;
        }
        __syncthreads();

        // ---- inputs = w_emb[out_id] ----
        if (t < HID) S[OF_XS + t] = __ldg(&w_emb[SI[IO_OUTID]*HID + t]);
        __syncthreads();

        // ---- lstm #2 ----
        cell(my_wih0, wr0, b0, &S[OF_XS], &S[OF_H0], &S[OF_C0], &S[OF_GBUF], t);
        cell(my_wih1, wr1, b1, &S[OF_H0], &S[OF_H1], &S[OF_C1], &S[OF_GBUF], t);

        // ---- w2out = out @ w_attn2.T ; append anchors ----
        if (t < HID) {
            const float4* w4 = (const float4*)&S[OF_WAT2 + t*PAD];
            const float4* h4 = (const float4*)&S[OF_H1];
            float a0 = 0.f, a1 = 0.f, a2 = 0.f, a3 = 0.f;
#pragma unroll
            for (int k = 0; k < 16; k++) {
                float4 wv = w4[k]; float4 hv = h4[k];
                a0 = fmaf(wv.x, hv.x, a0);
                a1 = fmaf(wv.y, hv.y, a1);
                a2 = fmaf(wv.z, hv.z, a2);
                a3 = fmaf(wv.w, hv.w, a3);
            }
            float v = (a0 + a1) + (a2 + a3);
            S[OF_W2OUT + t] = v;
            S[OF_AW1 + lid*HID + t] = v;
            S[OF_ANCH + lid*HID + t] = S[OF_H1 + t];
        }
        __syncthreads();

        if (lid > 0) {
            // ---- q_r = tanh(aw1[r] + w2out) . v_attn  (warp per row) ----
            {
                int warp = t >> 5, lane = t & 31;
                for (int r = warp; r < lid; r += 8) {
                    float s = ftanh(S[OF_AW1 + r*HID + lane] + S[OF_W2OUT + lane]) * S[OF_VATTN + lane]
                            + ftanh(S[OF_AW1 + r*HID + lane + 32] + S[OF_W2OUT + lane + 32]) * S[OF_VATTN + lane + 32];
#pragma unroll
                    for (int off = 16; off > 0; off >>= 1)
                        s += __shfl_down_sync(0xffffffffu, s, off);
                    if (lane == 0) S[OF_QV + r] = s;
                }
            }
            __syncthreads();

            // ---- per-row skip sample + stats ----
            if (t < lid) {
                float q  = S[OF_QV + t];
                float l0 = 1.5f * ftanh(q);
                float l1 = -l0;
                int gbase = OF_GUMS + lid*(lid-1) + 2*t;
                float g0 = S[gbase];
                float g1 = S[gbase + 1];
                float m   = fmaxf(l0, l1);
                float lsr = __logf(__expf(l0 - m) + __expf(l1 - m));
                float lp0 = (l0 - m) - lsr;
                float lp1 = (l1 - m) - lsr;
                int sk = (l1 + g1 > l0 + g0) ? 1 : 0;
                SI[IO_SKIPS + t] = (unsigned)sk;
                S[OF_RLP + t]  = sk ? lp1 : lp0;
                S[OF_RENT + t] = -(__expf(lp0) * lp0 + __expf(lp1) * lp1);
                float s0 = fsig(l0);
                float s1 = fsig(l1);
                S[OF_RKL + t] = s0 * __logf(__fdividef(s0, 0.8f))
                              + s1 * __logf(__fdividef(s1, 0.8f));
            }
            __syncthreads();

            if (t == 0) {
                int sc = 0;
                for (int i = 0; i < lid; i++) {
                    lp_sum  += S[OF_RLP + i];
                    ent_sum += S[OF_RENT + i];
                    kl_sum  += S[OF_RKL + i];
                    sc += (int)SI[IO_SKIPS + i];
                }
                S[OF_DEN] = 1.0f + (float)sc;
            }
            __syncthreads();

            if (t < HID) {
                float acc = 0.f;
                for (int i = 0; i < lid; i++)
                    acc += SI[IO_SKIPS + i] ? S[OF_ANCH + i*HID + t] : 0.0f;
                S[OF_XS + t] = acc / S[OF_DEN];
            }
            __syncthreads();
        } else {
            if (t < HID) S[OF_XS + t] = g_emb[t];
            __syncthreads();
        }
    }

    if (t == 0) {
        out3[0] = lp_sum;
        out3[1] = ent_sum;
        out3[2] = kl_sum;
    }
}

extern "C" void kernel_launch(void* const* d_in, const int* in_sizes, int n_in,
                              void* d_out, int out_size) {
    const float* g_emb   = (const float*)d_in[0];
    const float* w_emb   = (const float*)d_in[1];
    const float* w_soft  = (const float*)d_in[2];
    const float* w_attn2 = (const float*)d_in[3];
    const float* v_attn  = (const float*)d_in[4];
    const float* w_ih0   = (const float*)d_in[5];
    const float* w_hh0   = (const float*)d_in[6];
    const float* b_ih0   = (const float*)d_in[7];
    const float* b_hh0   = (const float*)d_in[8];
    const float* w_ih1   = (const float*)d_in[9];
    const float* w_hh1   = (const float*)d_in[10];
    const float* b_ih1   = (const float*)d_in[11];
    const float* b_hh1   = (const float*)d_in[12];
    const int*   seed    = (const int*)d_in[13];

    cudaFuncSetAttribute(enas_controller_kernel,
                         cudaFuncAttributeMaxDynamicSharedMemorySize, SMEM_BYTES);
    enas_controller_kernel<<<1, 256, SMEM_BYTES>>>(
        g_emb, w_emb, w_soft, w_attn2, v_attn,
        w_ih0, w_hh0, b_ih0, b_hh0,
        w_ih1, w_hh1, b_ih1, b_hh1,
        seed, (float*)d_out);
}

// round 3
// speedup vs baseline: 4.5676x; 1.0497x over previous
#include <cuda_runtime.h>

// ============================================================================
// EnasController R3: f32x2 packed FMA matvecs, per-gate activation spread over
// all warps, deferred stats (single final reduction), redundant argmax to cut
// barriers. One persistent block, 256 threads, ~171 KB dynamic smem.
// ============================================================================

#define N_LAYERS 12
#define NB 6
#define HID 64
#define PAD 68   // padded row stride (floats): stride%32==4 -> conflict-free LDS.128

typedef unsigned long long u64;

// ---- shared memory layout (float offsets) ----
#define OF_WIH0   0                        // 256*68
#define OF_WIH1   (OF_WIH0 + 256*PAD)
#define OF_WAT2   (OF_WIH1 + 256*PAD)      // 64*68
#define OF_BSUM0  (OF_WAT2 + 64*PAD)       // 256
#define OF_BSUM1  (OF_BSUM0 + 256)         // 256
#define OF_WSOFT  (OF_BSUM1 + 256)         // 6*64
#define OF_VATTN  (OF_WSOFT + NB*HID)      // 64
#define OF_XS     (OF_VATTN + 64)          // 64
#define OF_H0     (OF_XS + 64)
#define OF_C0     (OF_H0 + 64)
#define OF_H1     (OF_C0 + 64)
#define OF_C1     (OF_H1 + 64)
#define OF_GBUF   (OF_C1 + 64)             // 256
#define OF_ANCH   (OF_GBUF + 256)          // 12*64
#define OF_AW1    (OF_ANCH + N_LAYERS*64)  // 12*64
#define OF_W2OUT  (OF_AW1 + N_LAYERS*64)   // 64
#define OF_QV     (OF_W2OUT + 64)          // 16
#define OF_LOG6   (OF_QV + 16)             // 8
#define OF_GUMB   (OF_LOG6 + 8)            // 72
#define OF_GUMS   (OF_GUMB + 72)           // 132
#define OF_BLP    (OF_GUMS + 132)          // 12
#define OF_BENT   (OF_BLP + 12)            // 12
#define OF_SLP    (OF_BENT + 12)           // 66
#define OF_SENT   (OF_SLP + 66)            // 66
#define OF_SKL    (OF_SENT + 66)           // 66
#define OF_IREG   (OF_SKL + 66)            // uint region: 96
#define IO_SKIPS  0
#define IO_LKEY   16
#define IO_KB     (IO_LKEY + 24)
#define IO_KS     (IO_KB + 24)
#define SMEM_FLOATS (OF_IREG + 96)
#define SMEM_BYTES  (SMEM_FLOATS * 4)

#define FMA2(acc, w, x) \
    asm("fma.rn.f32x2 %0, %1, %2, %0;" : "+l"(acc) : "l"(w), "l"(x))

__device__ __forceinline__ float lo32(u64 v) { return __uint_as_float((unsigned)v); }
__device__ __forceinline__ float hi32(u64 v) { return __uint_as_float((unsigned)(v >> 32)); }

__device__ __forceinline__ unsigned rotl32(unsigned x, int r) {
    return (x << r) | (x >> (32 - r));
}

__device__ __forceinline__ void tf2x32(unsigned k0, unsigned k1,
                                       unsigned x0, unsigned x1,
                                       unsigned &o0, unsigned &o1) {
    const unsigned ks2 = k0 ^ k1 ^ 0x1BD11BDAu;
    x0 += k0; x1 += k1;
    x0+=x1; x1=rotl32(x1,13); x1^=x0;
    x0+=x1; x1=rotl32(x1,15); x1^=x0;
    x0+=x1; x1=rotl32(x1,26); x1^=x0;
    x0+=x1; x1=rotl32(x1, 6); x1^=x0;
    x0+=k1; x1+=ks2+1u;
    x0+=x1; x1=rotl32(x1,17); x1^=x0;
    x0+=x1; x1=rotl32(x1,29); x1^=x0;
    x0+=x1; x1=rotl32(x1,16); x1^=x0;
    x0+=x1; x1=rotl32(x1,24); x1^=x0;
    x0+=ks2; x1+=k0+2u;
    x0+=x1; x1=rotl32(x1,13); x1^=x0;
    x0+=x1; x1=rotl32(x1,15); x1^=x0;
    x0+=x1; x1=rotl32(x1,26); x1^=x0;
    x0+=x1; x1=rotl32(x1, 6); x1^=x0;
    x0+=k0; x1+=k1+3u;
    x0+=x1; x1=rotl32(x1,17); x1^=x0;
    x0+=x1; x1=rotl32(x1,29); x1^=x0;
    x0+=x1; x1=rotl32(x1,16); x1^=x0;
    x0+=x1; x1=rotl32(x1,24); x1^=x0;
    x0+=k1; x1+=ks2+4u;
    x0+=x1; x1=rotl32(x1,13); x1^=x0;
    x0+=x1; x1=rotl32(x1,15); x1^=x0;
    x0+=x1; x1=rotl32(x1,26); x1^=x0;
    x0+=x1; x1=rotl32(x1, 6); x1^=x0;
    x0+=ks2; x1+=k0+5u;
    o0 = x0; o1 = x1;
}

__device__ __forceinline__ unsigned rbits32(unsigned k0, unsigned k1, int idx) {
    unsigned o0, o1;
    tf2x32(k0, k1, 0u, (unsigned)idx, o0, o1);
    return o0 ^ o1;
}

__device__ __forceinline__ float gumbel_from_bits(unsigned bits) {
    const float TINY = 1.17549435e-38f;
    float f = __uint_as_float(0x3f800000u | (bits >> 9)) - 1.0f;
    float u = fmaxf(TINY, f + TINY);
    return -logf(-logf(u));   // accurate log: protects argmax agreement
}

__device__ __forceinline__ float fsig(float x) {
    return __fdividef(1.0f, 1.0f + __expf(-x));
}
__device__ __forceinline__ float ftanh(float x) {
    float ax = fabsf(x);
    float e  = __expf(-2.0f * ax);
    float r  = __fdividef(1.0f - e, 1.0f + e);
    return copysignf(r, x);
}

// One LSTM cell. wi: this thread's padded smem row (as packed pairs);
// wh: this thread's w_hh row in registers (32 x u64). 256 threads = gate rows.
__device__ __forceinline__ void cell(const ulonglong2* __restrict__ wi,
                                     const u64* __restrict__ wh,
                                     float bsum, bool is_g,
                                     const float* __restrict__ x,
                                     float* __restrict__ hio,
                                     float* __restrict__ c,
                                     float* __restrict__ gbuf, int t) {
    u64 a0 = (u64)__float_as_uint(bsum);  // lane0=bsum, lane1=0
    u64 a1 = 0ull, a2 = 0ull, a3 = 0ull;
    const ulonglong2* x2 = (const ulonglong2*)x;
    const ulonglong2* h2 = (const ulonglong2*)hio;
#pragma unroll
    for (int k = 0; k < 16; k += 2) {
        ulonglong2 w0 = wi[k];
        ulonglong2 w1 = wi[k + 1];
        ulonglong2 xv0 = x2[k];
        ulonglong2 xv1 = x2[k + 1];
        FMA2(a0, w0.x, xv0.x);
        FMA2(a1, w0.y, xv0.y);
        FMA2(a2, w1.x, xv1.x);
        FMA2(a3, w1.y, xv1.y);
    }
#pragma unroll
    for (int k = 0; k < 16; k += 2) {
        ulonglong2 hv0 = h2[k];
        ulonglong2 hv1 = h2[k + 1];
        FMA2(a0, wh[2*k],     hv0.x);
        FMA2(a1, wh[2*k + 1], hv0.y);
        FMA2(a2, wh[2*k + 2], hv1.x);
        FMA2(a3, wh[2*k + 3], hv1.y);
    }
    float g = ((lo32(a0) + hi32(a0)) + (lo32(a1) + hi32(a1)))
            + ((lo32(a2) + hi32(a2)) + (lo32(a3) + hi32(a3)));
    gbuf[t] = is_g ? ftanh(g) : fsig(g);   // per-gate activation, all 8 warps
    __syncthreads();
    if (t < HID) {
        float cn = gbuf[HID + t] * c[t] + gbuf[t] * gbuf[2*HID + t];
        c[t] = cn;
        hio[t] = gbuf[3*HID + t] * ftanh(cn);
    }
    __syncthreads();
}

__global__ __launch_bounds__(256, 1)
void enas_controller_kernel(const float* __restrict__ g_emb,
                            const float* __restrict__ w_emb,
                            const float* __restrict__ w_soft,
                            const float* __restrict__ w_attn2,
                            const float* __restrict__ v_attn,
                            const float* __restrict__ w_ih0,
                            const float* __restrict__ w_hh0,
                            const float* __restrict__ b_ih0,
                            const float* __restrict__ b_hh0,
                            const float* __restrict__ w_ih1,
                            const float* __restrict__ w_hh1,
                            const float* __restrict__ b_ih1,
                            const float* __restrict__ b_hh1,
                            const int* __restrict__ seed_p,
                            float* __restrict__ out3) {
    extern __shared__ __align__(16) float S[];
    unsigned* SI = (unsigned*)&S[OF_IREG];
    const int t = threadIdx.x;
    const bool is_g = ((t >> 6) == 2);

    // ---- stage w_ih0 / w_ih1 / w_attn2 into padded smem ----
    {
        const float4* g0 = (const float4*)w_ih0;
        const float4* g1 = (const float4*)w_ih1;
        for (int idx = t; idx < 256*16; idx += 256) {
            int row = idx >> 4, col = idx & 15;
            *(float4*)&S[OF_WIH0 + row*PAD + col*4] = __ldg(&g0[idx]);
            *(float4*)&S[OF_WIH1 + row*PAD + col*4] = __ldg(&g1[idx]);
        }
        const float4* ga = (const float4*)w_attn2;
        for (int idx = t; idx < 64*16; idx += 256) {
            int row = idx >> 4, col = idx & 15;
            *(float4*)&S[OF_WAT2 + row*PAD + col*4] = __ldg(&ga[idx]);
        }
        const float4* gs = (const float4*)w_soft;
        if (t < NB*16) *(float4*)&S[OF_WSOFT + t*4] = __ldg(&gs[t]);
        S[OF_BSUM0 + t] = __ldg(&b_ih0[t]) + __ldg(&b_hh0[t]);
        S[OF_BSUM1 + t] = __ldg(&b_ih1[t]) + __ldg(&b_hh1[t]);
        if (t < HID) {
            S[OF_VATTN + t] = __ldg(&v_attn[t]);
            S[OF_XS + t] = g_emb[t];
            S[OF_H0 + t] = 0.f; S[OF_C0 + t] = 0.f;
            S[OF_H1 + t] = 0.f; S[OF_C1 + t] = 0.f;
        }
    }

    // ---- w_hh rows into registers as packed pairs ----
    u64 wh0[32], wh1[32];
    {
        const ulonglong2* p0 = (const ulonglong2*)(w_hh0 + t*HID);
        const ulonglong2* p1 = (const ulonglong2*)(w_hh1 + t*HID);
#pragma unroll
        for (int k = 0; k < 16; k++) {
            ulonglong2 v0 = __ldg(&p0[k]);
            ulonglong2 v1 = __ldg(&p1[k]);
            wh0[2*k] = v0.x; wh0[2*k + 1] = v0.y;
            wh1[2*k] = v1.x; wh1[2*k + 1] = v1.y;
        }
    }

    // ---- RNG precompute ----
    if (t == 0) {
        unsigned k0 = 0u, k1 = (unsigned)seed_p[0];
        for (int l = 0; l < N_LAYERS; l++) {
            SI[IO_LKEY + 2*l]     = k0;
            SI[IO_LKEY + 2*l + 1] = k1;
            unsigned a0, a1;
            tf2x32(k0, k1, 0u, 0u, a0, a1);
            k0 = a0; k1 = a1;
        }
    }
    __syncthreads();
    if (t < 24) {
        int l = t >> 1, which = t & 1;   // 0 -> kb (x1=1), 1 -> ks (x1=2)
        unsigned o0, o1;
        tf2x32(SI[IO_LKEY + 2*l], SI[IO_LKEY + 2*l + 1], 0u, (unsigned)(1 + which), o0, o1);
        int base = which ? IO_KS : IO_KB;
        SI[base + 2*l] = o0; SI[base + 2*l + 1] = o1;
    }
    __syncthreads();
    if (t < 72) {
        int l = t / NB, j = t % NB;
        S[OF_GUMB + l*NB + j] =
            gumbel_from_bits(rbits32(SI[IO_KB + 2*l], SI[IO_KB + 2*l + 1], j));
    } else if (t < 72 + 132) {
        int f = t - 72;                  // layer l occupies [l*(l-1), l*(l+1))
        int l = 1;
        while (f >= l*(l+1)) l++;
        int j = f - l*(l-1);
        S[OF_GUMS + f] =
            gumbel_from_bits(rbits32(SI[IO_KS + 2*l], SI[IO_KS + 2*l + 1], j));
    }
    __syncthreads();

    const ulonglong2* my_wi0 = (const ulonglong2*)&S[OF_WIH0 + t*PAD];
    const ulonglong2* my_wi1 = (const ulonglong2*)&S[OF_WIH1 + t*PAD];
    const float b0 = S[OF_BSUM0 + t];
    const float b1 = S[OF_BSUM1 + t];

#pragma unroll 1
    for (int lid = 0; lid < N_LAYERS; ++lid) {
        // ---- lstm call #1 ----
        cell(my_wi0, wh0, b0, is_g, &S[OF_XS], &S[OF_H0], &S[OF_C0], &S[OF_GBUF], t);
        cell(my_wi1, wh1, b1, is_g, &S[OF_H0], &S[OF_H1], &S[OF_C1], &S[OF_GBUF], t);

        // ---- logits = w_soft @ h1 (6 threads, packed) ----
        if (t < NB) {
            const ulonglong2* w2 = (const ulonglong2*)&S[OF_WSOFT + t*HID];
            const ulonglong2* h2 = (const ulonglong2*)&S[OF_H1];
            u64 a0 = 0ull, a1 = 0ull, a2 = 0ull, a3 = 0ull;
#pragma unroll
            for (int k = 0; k < 16; k += 2) {
                ulonglong2 wv0 = w2[k], hv0 = h2[k];
                ulonglong2 wv1 = w2[k+1], hv1 = h2[k+1];
                FMA2(a0, wv0.x, hv0.x);
                FMA2(a1, wv0.y, hv0.y);
                FMA2(a2, wv1.x, hv1.x);
                FMA2(a3, wv1.y, hv1.y);
            }
            S[OF_LOG6 + t] = ((lo32(a0)+hi32(a0)) + (lo32(a1)+hi32(a1)))
                           + ((lo32(a2)+hi32(a2)) + (lo32(a3)+hi32(a3)));
        }
        __syncthreads();

        // ---- sample phase: t<64 redundant argmax + xs load; t==64 stats ----
        if (t < HID) {
            float bz = S[OF_LOG6] + S[OF_GUMB + lid*NB];
            int best = 0;
#pragma unroll
            for (int j = 1; j < NB; j++) {
                float z = S[OF_LOG6 + j] + S[OF_GUMB + lid*NB + j];
                if (z > bz) { bz = z; best = j; }
            }
            S[OF_XS + t] = __ldg(&w_emb[best*HID + t]);
        } else if (t == 64) {
            float l[NB];
#pragma unroll
            for (int j = 0; j < NB; j++) l[j] = S[OF_LOG6 + j];
            float m = l[0];
#pragma unroll
            for (int j = 1; j < NB; j++) m = fmaxf(m, l[j]);
            float s = 0.f;
#pragma unroll
            for (int j = 0; j < NB; j++) s += __expf(l[j] - m);
            float lse = __logf(s);
            int best = 0;
            float bz = l[0] + S[OF_GUMB + lid*NB];
#pragma unroll
            for (int j = 1; j < NB; j++) {
                float z = l[j] + S[OF_GUMB + lid*NB + j];
                if (z > bz) { bz = z; best = j; }
            }
            S[OF_BLP + lid] = (l[best] - m) - lse;
            float ent = 0.f;
#pragma unroll
            for (int j = 0; j < NB; j++) {
                float lp = (l[j] - m) - lse;
                ent -= __expf(lp) * lp;
            }
            S[OF_BENT + lid] = ent;
        }
        __syncthreads();

        // ---- lstm call #2 ----
        cell(my_wi0, wh0, b0, is_g, &S[OF_XS], &S[OF_H0], &S[OF_C0], &S[OF_GBUF], t);
        cell(my_wi1, wh1, b1, is_g, &S[OF_H0], &S[OF_H1], &S[OF_C1], &S[OF_GBUF], t);

        // ---- w2out = h1 @ w_attn2.T ; append anchors ----
        if (t < HID) {
            const ulonglong2* w2 = (const ulonglong2*)&S[OF_WAT2 + t*PAD];
            const ulonglong2* h2 = (const ulonglong2*)&S[OF_H1];
            u64 a0 = 0ull, a1 = 0ull, a2 = 0ull, a3 = 0ull;
#pragma unroll
            for (int k = 0; k < 16; k += 2) {
                ulonglong2 wv0 = w2[k], hv0 = h2[k];
                ulonglong2 wv1 = w2[k+1], hv1 = h2[k+1];
                FMA2(a0, wv0.x, hv0.x);
                FMA2(a1, wv0.y, hv0.y);
                FMA2(a2, wv1.x, hv1.x);
                FMA2(a3, wv1.y, hv1.y);
            }
            float v = ((lo32(a0)+hi32(a0)) + (lo32(a1)+hi32(a1)))
                    + ((lo32(a2)+hi32(a2)) + (lo32(a3)+hi32(a3)));
            S[OF_W2OUT + t] = v;
            S[OF_AW1 + lid*HID + t] = v;
            S[OF_ANCH + lid*HID + t] = S[OF_H1 + t];
        }
        __syncthreads();

        if (lid > 0) {
            // ---- q_r = tanh(aw1[r] + w2out) . v_attn (warp per row) ----
            {
                int warp = t >> 5, lane = t & 31;
                for (int r = warp; r < lid; r += 8) {
                    float s = ftanh(S[OF_AW1 + r*HID + lane] + S[OF_W2OUT + lane]) * S[OF_VATTN + lane]
                            + ftanh(S[OF_AW1 + r*HID + lane + 32] + S[OF_W2OUT + lane + 32]) * S[OF_VATTN + lane + 32];
#pragma unroll
                    for (int off = 16; off > 0; off >>= 1)
                        s += __shfl_down_sync(0xffffffffu, s, off);
                    if (lane == 0) S[OF_QV + r] = s;
                }
            }
            __syncthreads();

            // ---- warp 0: cheap skip decision; warp 1: heavy per-row stats ----
            if (t < lid) {
                float l0 = 1.5f * ftanh(S[OF_QV + t]);
                int gbase = OF_GUMS + lid*(lid-1) + 2*t;
                float g0 = S[gbase], g1 = S[gbase + 1];
                SI[IO_SKIPS + t] = ((-l0) + g1 > l0 + g0) ? 1u : 0u;
            } else if (t >= 32 && t < 32 + lid) {
                int r = t - 32;
                float l0 = 1.5f * ftanh(S[OF_QV + r]);
                float l1 = -l0;
                int gbase = OF_GUMS + lid*(lid-1) + 2*r;
                float g0 = S[gbase], g1 = S[gbase + 1];
                float m = fmaxf(l0, l1);
                float lsr = __logf(__expf(l0 - m) + __expf(l1 - m));
                float lp0 = (l0 - m) - lsr;
                float lp1 = (l1 - m) - lsr;
                int slot = (lid*(lid-1))/2 + r;
                S[OF_SLP + slot]  = (l1 + g1 > l0 + g0) ? lp1 : lp0;
                S[OF_SENT + slot] = -(__expf(lp0)*lp0 + __expf(lp1)*lp1);
                float s0 = fsig(l0), s1 = fsig(l1);
                S[OF_SKL + slot] = s0 * __logf(__fdividef(s0, 0.8f))
                                 + s1 * __logf(__fdividef(s1, 0.8f));
            }
            __syncthreads();

            // ---- xs = (skips @ anchors) / (1 + sc), redundant sc in t<64 ----
            if (t < HID) {
                int sc = 0;
                float acc = 0.f;
                for (int i = 0; i < lid; i++) {
                    unsigned sk = SI[IO_SKIPS + i];
                    sc += (int)sk;
                    acc += sk ? S[OF_ANCH + i*HID + t] : 0.0f;
                }
                S[OF_XS + t] = __fdividef(acc, 1.0f + (float)sc);
            }
            __syncthreads();
        } else {
            if (t < HID) S[OF_XS + t] = g_emb[t];
            __syncthreads();
        }
    }

    // ---- final reduction of deferred stats ----
    if (t < 32) {
        float s1 = 0.f, s2 = 0.f, s3 = 0.f;
        for (int i = t; i < 12; i += 32) { s1 += S[OF_BLP + i]; s2 += S[OF_BENT + i]; }
        for (int i = t; i < 66; i += 32) {
            s1 += S[OF_SLP + i]; s2 += S[OF_SENT + i]; s3 += S[OF_SKL + i];
        }
#pragma unroll
        for (int off = 16; off > 0; off >>= 1) {
            s1 += __shfl_down_sync(0xffffffffu, s1, off);
            s2 += __shfl_down_sync(0xffffffffu, s2, off);
            s3 += __shfl_down_sync(0xffffffffu, s3, off);
        }
        if (t == 0) {
            out3[0] = s1;
            out3[1] = s2;
            out3[2] = s3;
        }
    }
}

extern "C" void kernel_launch(void* const* d_in, const int* in_sizes, int n_in,
                              void* d_out, int out_size) {
    const float* g_emb   = (const float*)d_in[0];
    const float* w_emb   = (const float*)d_in[1];
    const float* w_soft  = (const float*)d_in[2];
    const float* w_attn2 = (const float*)d_in[3];
    const float* v_attn  = (const float*)d_in[4];
    const float* w_ih0   = (const float*)d_in[5];
    const float* w_hh0   = (const float*)d_in[6];
    const float* b_ih0   = (const float*)d_in[7];
    const float* b_hh0   = (const float*)d_in[8];
    const float* w_ih1   = (const float*)d_in[9];
    const float* w_hh1   = (const float*)d_in[10];
    const float* b_ih1   = (const float*)d_in[11];
    const float* b_hh1   = (const float*)d_in[12];
    const int*   seed    = (const int*)d_in[13];

    cudaFuncSetAttribute(enas_controller_kernel,
                         cudaFuncAttributeMaxDynamicSharedMemorySize, SMEM_BYTES);
    enas_controller_kernel<<<1, 256, SMEM_BYTES>>>(
        g_emb, w_emb, w_soft, w_attn2, v_attn,
        w_ih0, w_hh0, b_ih0, b_hh0,
        w_ih1, w_hh1, b_ih1, b_hh1,
        seed, (float*)d_out);
}

// round 4
// speedup vs baseline: 4.6413x; 1.0161x over previous
#include <cuda_runtime.h>

// ============================================================================
// EnasController R4: single-barrier LSTM cells (in-warp gate layout + shuffle
// epilogue, c in registers, ping-pong h buffers), P-table for all known-input
// cells (14/24 layer-0 cells become RF-only), 8-thread attention rows.
// One persistent block, 256 threads.
// ============================================================================

#define N_LAYERS 12
#define NB 6
#define HID 64
#define PAD 68   // 68-float row stride: (row*17+chunk)%8 distinct per 8-lane phase

typedef unsigned long long u64;

// ---- shared memory layout (float offsets) ----
#define OF_WI0   0                        // 256*68
#define OF_WI1   (OF_WI0 + 256*PAD)       // 256*68
#define OF_WAT2  (OF_WI1 + 256*PAD)       // 64*68
#define OF_WSOFT (OF_WAT2 + 64*PAD)       // 6*64
#define OF_VATTN (OF_WSOFT + NB*HID)      // 64
#define OF_WEMB  (OF_VATTN + 64)          // 6*64
#define OF_GEMB  (OF_WEMB + NB*HID)       // 64
#define OF_P     (OF_GEMB + 64)           // 7*256
#define OF_XS    (OF_P + 7*256)           // 64
#define OF_H0A   (OF_XS + 64)
#define OF_H0B   (OF_H0A + 64)
#define OF_H1A   (OF_H0B + 64)
#define OF_H1B   (OF_H1A + 64)
#define OF_ANCH  (OF_H1B + 64)            // 12*64
#define OF_AW1   (OF_ANCH + 12*64)        // 12*64
#define OF_W2OUT (OF_AW1 + 12*64)         // 64
#define OF_QV    (OF_W2OUT + 64)          // 16
#define OF_LOG6  (OF_QV + 16)             // 8
#define OF_GUMB  (OF_LOG6 + 8)            // 72
#define OF_GUMS  (OF_GUMB + 72)           // 132
#define OF_BLP   (OF_GUMS + 132)          // 12
#define OF_BENT  (OF_BLP + 12)            // 12
#define OF_SLP   (OF_BENT + 12)           // 66
#define OF_SENT  (OF_SLP + 66)            // 66
#define OF_SKL   (OF_SENT + 66)           // 66
#define OF_IREG  (OF_SKL + 66)            // uint region: 96
#define IO_SKIPS 0
#define IO_BEST  16
#define IO_LKEY  18
#define IO_KB    (IO_LKEY + 24)
#define IO_KS    (IO_KB + 24)
#define SMEM_FLOATS (OF_IREG + 96)
#define SMEM_BYTES  (SMEM_FLOATS * 4)

#define FMA2(acc, w, x) \
    asm("fma.rn.f32x2 %0, %1, %2, %0;" : "+l"(acc) : "l"(w), "l"(x))

__device__ __forceinline__ float lo32(u64 v) { return __uint_as_float((unsigned)v); }
__device__ __forceinline__ float hi32(u64 v) { return __uint_as_float((unsigned)(v >> 32)); }

__device__ __forceinline__ unsigned rotl32(unsigned x, int r) {
    return (x << r) | (x >> (32 - r));
}

__device__ __forceinline__ void tf2x32(unsigned k0, unsigned k1,
                                       unsigned x0, unsigned x1,
                                       unsigned &o0, unsigned &o1) {
    const unsigned ks2 = k0 ^ k1 ^ 0x1BD11BDAu;
    x0 += k0; x1 += k1;
    x0+=x1; x1=rotl32(x1,13); x1^=x0;
    x0+=x1; x1=rotl32(x1,15); x1^=x0;
    x0+=x1; x1=rotl32(x1,26); x1^=x0;
    x0+=x1; x1=rotl32(x1, 6); x1^=x0;
    x0+=k1; x1+=ks2+1u;
    x0+=x1; x1=rotl32(x1,17); x1^=x0;
    x0+=x1; x1=rotl32(x1,29); x1^=x0;
    x0+=x1; x1=rotl32(x1,16); x1^=x0;
    x0+=x1; x1=rotl32(x1,24); x1^=x0;
    x0+=ks2; x1+=k0+2u;
    x0+=x1; x1=rotl32(x1,13); x1^=x0;
    x0+=x1; x1=rotl32(x1,15); x1^=x0;
    x0+=x1; x1=rotl32(x1,26); x1^=x0;
    x0+=x1; x1=rotl32(x1, 6); x1^=x0;
    x0+=k0; x1+=k1+3u;
    x0+=x1; x1=rotl32(x1,17); x1^=x0;
    x0+=x1; x1=rotl32(x1,29); x1^=x0;
    x0+=x1; x1=rotl32(x1,16); x1^=x0;
    x0+=x1; x1=rotl32(x1,24); x1^=x0;
    x0+=k1; x1+=ks2+4u;
    x0+=x1; x1=rotl32(x1,13); x1^=x0;
    x0+=x1; x1=rotl32(x1,15); x1^=x0;
    x0+=x1; x1=rotl32(x1,26); x1^=x0;
    x0+=x1; x1=rotl32(x1, 6); x1^=x0;
    x0+=ks2; x1+=k0+5u;
    o0 = x0; o1 = x1;
}

__device__ __forceinline__ unsigned rbits32(unsigned k0, unsigned k1, int idx) {
    unsigned o0, o1;
    tf2x32(k0, k1, 0u, (unsigned)idx, o0, o1);
    return o0 ^ o1;
}

__device__ __forceinline__ float gumbel_from_bits(unsigned bits) {
    const float TINY = 1.17549435e-38f;
    float f = __uint_as_float(0x3f800000u | (bits >> 9)) - 1.0f;
    float u = fmaxf(TINY, f + TINY);
    return -logf(-logf(u));   // accurate log: protects argmax agreement
}

__device__ __forceinline__ float fsig(float x) {
    return __fdividef(1.0f, 1.0f + __expf(-x));
}
__device__ __forceinline__ float ftanh(float x) {
    float ax = fabsf(x);
    float e  = __expf(-2.0f * ax);
    float r  = __fdividef(1.0f - e, 1.0f + e);
    return copysignf(r, x);
}

// dot of a 64-float smem row (as packed pairs) with a 64-float smem vector
__device__ __forceinline__ float dot64p(const ulonglong2* __restrict__ w,
                                        const ulonglong2* __restrict__ v) {
    u64 a0 = 0ull, a1 = 0ull, a2 = 0ull, a3 = 0ull;
#pragma unroll
    for (int k = 0; k < 16; k += 2) {
        ulonglong2 w0 = w[k], w1 = w[k + 1];
        ulonglong2 v0 = v[k], v1 = v[k + 1];
        FMA2(a0, w0.x, v0.x);
        FMA2(a1, w0.y, v0.y);
        FMA2(a2, w1.x, v1.x);
        FMA2(a3, w1.y, v1.y);
    }
    return ((lo32(a0) + hi32(a0)) + (lo32(a1) + hi32(a1)))
         + ((lo32(a2) + hi32(a2)) + (lo32(a3) + hi32(a3)));
}

// dot of a register-resident row (32 packed pairs) with a smem vector
__device__ __forceinline__ float dot64r(const u64* __restrict__ w,
                                        const ulonglong2* __restrict__ v) {
    u64 a0 = 0ull, a1 = 0ull, a2 = 0ull, a3 = 0ull;
#pragma unroll
    for (int k = 0; k < 16; k += 2) {
        ulonglong2 v0 = v[k], v1 = v[k + 1];
        FMA2(a0, w[2*k],     v0.x);
        FMA2(a1, w[2*k + 1], v0.y);
        FMA2(a2, w[2*k + 2], v1.x);
        FMA2(a3, w[2*k + 3], v1.y);
    }
    return ((lo32(a0) + hi32(a0)) + (lo32(a1) + hi32(a1)))
         + ((lo32(a2) + hi32(a2)) + (lo32(a3) + hi32(a3)));
}

// Epilogue: lane l holds pre-activation for gate (l>>3), row w*8+(l&7).
// Combine gates via intra-warp shuffles; c lives in registers (4x redundant).
__device__ __forceinline__ void epilogue(float acc, float& c,
                                         float* __restrict__ hout,
                                         int l, int rowIdx) {
    int grp = l >> 3, r8 = l & 7;
    float act = (grp == 2) ? ftanh(acc) : fsig(acc);
    float ai = __shfl_sync(0xffffffffu, act, r8);
    float af = __shfl_sync(0xffffffffu, act, r8 + 8);
    float ag = __shfl_sync(0xffffffffu, act, r8 + 16);
    float ao = __shfl_sync(0xffffffffu, act, r8 + 24);
    float cn = af * c + ai * ag;
    c = cn;
    float hv = ao * ftanh(cn);
    if (l < 8) hout[rowIdx] = hv;
    __syncthreads();
}

__global__ __launch_bounds__(256, 1)
void enas_controller_kernel(const float* __restrict__ g_emb,
                            const float* __restrict__ w_emb,
                            const float* __restrict__ w_soft,
                            const float* __restrict__ w_attn2,
                            const float* __restrict__ v_attn,
                            const float* __restrict__ w_ih0,
                            const float* __restrict__ w_hh0,
                            const float* __restrict__ b_ih0,
                            const float* __restrict__ b_hh0,
                            const float* __restrict__ w_ih1,
                            const float* __restrict__ w_hh1,
                            const float* __restrict__ b_ih1,
                            const float* __restrict__ b_hh1,
                            const int* __restrict__ seed_p,
                            float* __restrict__ out3) {
    extern __shared__ __align__(16) float S[];
    unsigned* SI = (unsigned*)&S[OF_IREG];
    const int t = threadIdx.x;
    const int w = t >> 5, l = t & 31;
    const int grp = l >> 3, r8 = l & 7;
    const int rowIdx = w * 8 + r8;            // 0..63
    const int R = grp * 64 + rowIdx;          // this thread's gate row 0..255

    // ---- stage weights into smem (linear, coalesced) ----
    {
        const float4* g0 = (const float4*)w_ih0;
        const float4* g1 = (const float4*)w_ih1;
        for (int idx = t; idx < 256*16; idx += 256) {
            int row = idx >> 4, col = idx & 15;
            *(float4*)&S[OF_WI0 + row*PAD + col*4] = __ldg(&g0[idx]);
            *(float4*)&S[OF_WI1 + row*PAD + col*4] = __ldg(&g1[idx]);
        }
        const float4* ga = (const float4*)w_attn2;
        for (int idx = t; idx < 64*16; idx += 256) {
            int row = idx >> 4, col = idx & 15;
            *(float4*)&S[OF_WAT2 + row*PAD + col*4] = __ldg(&ga[idx]);
        }
        const float4* gs = (const float4*)w_soft;
        if (t < NB*16) *(float4*)&S[OF_WSOFT + t*4] = __ldg(&gs[t]);
        const float4* ge = (const float4*)w_emb;
        if (t >= 32 && t < 32 + NB*16) *(float4*)&S[OF_WEMB + (t-32)*4] = __ldg(&ge[t-32]);
        if (t >= 128 && t < 144) *(float4*)&S[OF_GEMB + (t-128)*4] = __ldg(&((const float4*)g_emb)[t-128]);
        if (t >= 160 && t < 160 + HID) {
            S[OF_VATTN + t - 160] = __ldg(&v_attn[t - 160]);
            S[OF_H0A + t - 160] = 0.f;
            S[OF_H1A + t - 160] = 0.f;
        }
    }

    // ---- per-thread row data: w_hh rows in registers, bias sums ----
    u64 wh0[32], wh1[32];
    {
        const ulonglong2* p0 = (const ulonglong2*)(w_hh0 + R*HID);
        const ulonglong2* p1 = (const ulonglong2*)(w_hh1 + R*HID);
#pragma unroll
        for (int k = 0; k < 16; k++) {
            ulonglong2 v0 = __ldg(&p0[k]);
            ulonglong2 v1 = __ldg(&p1[k]);
            wh0[2*k] = v0.x; wh0[2*k + 1] = v0.y;
            wh1[2*k] = v1.x; wh1[2*k + 1] = v1.y;
        }
    }
    const float b0R = __ldg(&b_ih0[R]) + __ldg(&b_hh0[R]);
    const float b1R = __ldg(&b_ih1[R]) + __ldg(&b_hh1[R]);

    // ---- RNG precompute: serial key chain, then keys + all gumbels ----
    if (t == 0) {
        unsigned k0 = 0u, k1 = (unsigned)seed_p[0];
        for (int lid = 0; lid < N_LAYERS; lid++) {
            SI[IO_LKEY + 2*lid]     = k0;
            SI[IO_LKEY + 2*lid + 1] = k1;
            unsigned a0, a1;
            tf2x32(k0, k1, 0u, 0u, a0, a1);
            k0 = a0; k1 = a1;
        }
    }
    __syncthreads();
    if (t < 24) {
        int lid = t >> 1, which = t & 1;   // 0 -> kb (x1=1), 1 -> ks (x1=2)
        unsigned o0, o1;
        tf2x32(SI[IO_LKEY + 2*lid], SI[IO_LKEY + 2*lid + 1], 0u, (unsigned)(1 + which), o0, o1);
        int base = which ? IO_KS : IO_KB;
        SI[base + 2*lid] = o0; SI[base + 2*lid + 1] = o1;
    }
    // ---- P table: P[b][R] = bsum0[R] + w_ih0[R,:] . vec_b  (b=0..5 emb, 6=gemb)
    {
        const ulonglong2* wrow = (const ulonglong2*)&S[OF_WI0 + R*PAD];
        // wi0 staging done pre-barrier above; w_emb/g_emb staged too.
#pragma unroll
        for (int b = 0; b < 7; b++) {
            const ulonglong2* vec = (const ulonglong2*)
                ((b < 6) ? &S[OF_WEMB + b*HID] : &S[OF_GEMB]);
            S[OF_P + b*256 + R] = b0R + dot64p(wrow, vec);
        }
    }
    __syncthreads();
    if (t < 72) {
        int lid = t / NB, j = t % NB;
        S[OF_GUMB + lid*NB + j] =
            gumbel_from_bits(rbits32(SI[IO_KB + 2*lid], SI[IO_KB + 2*lid + 1], j));
    } else if (t < 72 + 132) {
        int f = t - 72;                   // layer lid occupies [lid*(lid-1), lid*(lid+1))
        int lid = 1;
        while (f >= lid*(lid+1)) lid++;
        int j = f - lid*(lid-1);
        S[OF_GUMS + f] =
            gumbel_from_bits(rbits32(SI[IO_KS + 2*lid], SI[IO_KS + 2*lid + 1], j));
    }
    __syncthreads();

    const ulonglong2* wi0row = (const ulonglong2*)&S[OF_WI0 + R*PAD];
    const ulonglong2* wi1row = (const ulonglong2*)&S[OF_WI1 + R*PAD];
    float c0 = 0.f, c1 = 0.f;

#pragma unroll 1
    for (int lid = 0; lid < N_LAYERS; ++lid) {
        // ================= lstm call #1 =================
        // cell0: input = g_emb (lid<2, P[6]) or skip-avg xs (heavy).
        // reads h0A, writes h0B
        {
            float acc;
            if (lid < 2) {
                acc = S[OF_P + 6*256 + R]
                    + dot64r(wh0, (const ulonglong2*)&S[OF_H0A]);
            } else {
                acc = b0R + dot64p(wi0row, (const ulonglong2*)&S[OF_XS])
                    + dot64r(wh0, (const ulonglong2*)&S[OF_H0A]);
            }
            epilogue(acc, c0, &S[OF_H0B], l, rowIdx);
        }
        // cell1: x = h0B, reads h1A, writes h1B
        {
            float acc = b1R + dot64p(wi1row, (const ulonglong2*)&S[OF_H0B])
                      + dot64r(wh1, (const ulonglong2*)&S[OF_H1A]);
            epilogue(acc, c1, &S[OF_H1B], l, rowIdx);
        }

        // ---- logits = w_soft @ h1B ----
        if (t < NB) {
            S[OF_LOG6 + t] = dot64p((const ulonglong2*)&S[OF_WSOFT + t*HID],
                                    (const ulonglong2*)&S[OF_H1B]);
        }
        __syncthreads();

        // ---- sample: t0 picks best; t64 computes branch stats ----
        if (t == 0) {
            float bz = S[OF_LOG6] + S[OF_GUMB + lid*NB];
            int best = 0;
#pragma unroll
            for (int j = 1; j < NB; j++) {
                float z = S[OF_LOG6 + j] + S[OF_GUMB + lid*NB + j];
                if (z > bz) { bz = z; best = j; }
            }
            SI[IO_BEST] = (unsigned)best;
        } else if (t == 64) {
            float lv[NB];
#pragma unroll
            for (int j = 0; j < NB; j++) lv[j] = S[OF_LOG6 + j];
            float m = lv[0];
#pragma unroll
            for (int j = 1; j < NB; j++) m = fmaxf(m, lv[j]);
            float s = 0.f;
#pragma unroll
            for (int j = 0; j < NB; j++) s += __expf(lv[j] - m);
            float lse = __logf(s);
            int best = 0;
            float bz = lv[0] + S[OF_GUMB + lid*NB];
#pragma unroll
            for (int j = 1; j < NB; j++) {
                float z = lv[j] + S[OF_GUMB + lid*NB + j];
                if (z > bz) { bz = z; best = j; }
            }
            S[OF_BLP + lid] = (lv[best] - m) - lse;
            float ent = 0.f;
#pragma unroll
            for (int j = 0; j < NB; j++) {
                float lp = (lv[j] - m) - lse;
                ent -= __expf(lp) * lp;
            }
            S[OF_BENT + lid] = ent;
        }
        __syncthreads();

        // ================= lstm call #2 =================
        // cell0 (light, P[best]): reads h0B, writes h0A
        {
            float acc = S[OF_P + (int)SI[IO_BEST]*256 + R]
                      + dot64r(wh0, (const ulonglong2*)&S[OF_H0B]);
            epilogue(acc, c0, &S[OF_H0A], l, rowIdx);
        }
        // cell1: x = h0A, reads h1B, writes h1A
        {
            float acc = b1R + dot64p(wi1row, (const ulonglong2*)&S[OF_H0A])
                      + dot64r(wh1, (const ulonglong2*)&S[OF_H1B]);
            epilogue(acc, c1, &S[OF_H1A], l, rowIdx);
        }

        // ---- anchor phase: w2out = h1A @ w_attn2.T; append aw1, anchors ----
        if (t < HID) {
            float v = dot64p((const ulonglong2*)&S[OF_WAT2 + t*PAD],
                             (const ulonglong2*)&S[OF_H1A]);
            S[OF_W2OUT + t] = v;
            S[OF_AW1 + lid*HID + t] = v;
            S[OF_ANCH + lid*HID + t] = S[OF_H1A + t];
        }
        __syncthreads();

        if (lid > 0) {
            // ---- attention: q_r = tanh(aw1[r] + w2out) . v_attn
            //      8 threads per row, warps 0-2 (rows clamped) ----
            if (w < 3) {
                int r = t >> 3, j0 = t & 7;
                int rc = (r < lid) ? r : 0;
                float s = 0.f;
#pragma unroll
                for (int k = 0; k < 8; k++) {
                    int j = j0 + 8*k;
                    s += ftanh(S[OF_AW1 + rc*HID + j] + S[OF_W2OUT + j]) * S[OF_VATTN + j];
                }
                s += __shfl_down_sync(0xffffffffu, s, 4, 8);
                s += __shfl_down_sync(0xffffffffu, s, 2, 8);
                s += __shfl_down_sync(0xffffffffu, s, 1, 8);
                if (j0 == 0 && r < lid) S[OF_QV + r] = s;
            }
            __syncthreads();

            // ---- warp 0: skip decisions; warp 1: per-row stats ----
            if (t < lid) {
                float l0 = 1.5f * ftanh(S[OF_QV + t]);
                int gbase = OF_GUMS + lid*(lid-1) + 2*t;
                float g0 = S[gbase], g1 = S[gbase + 1];
                SI[IO_SKIPS + t] = ((-l0) + g1 > l0 + g0) ? 1u : 0u;
            } else if (t >= 32 && t < 32 + lid) {
                int r = t - 32;
                float l0 = 1.5f * ftanh(S[OF_QV + r]);
                float l1 = -l0;
                int gbase = OF_GUMS + lid*(lid-1) + 2*r;
                float g0 = S[gbase], g1 = S[gbase + 1];
                float m = fmaxf(l0, l1);
                float lsr = __logf(__expf(l0 - m) + __expf(l1 - m));
                float lp0 = (l0 - m) - lsr;
                float lp1 = (l1 - m) - lsr;
                int slot = (lid*(lid-1))/2 + r;
                S[OF_SLP + slot]  = (l1 + g1 > l0 + g0) ? lp1 : lp0;
                S[OF_SENT + slot] = -(__expf(lp0)*lp0 + __expf(lp1)*lp1);
                float s0 = fsig(l0), s1 = fsig(l1);
                S[OF_SKL + slot] = s0 * __logf(__fdividef(s0, 0.8f))
                                 + s1 * __logf(__fdividef(s1, 0.8f));
            }
            __syncthreads();

            // ---- xs = (skips @ anchors) / (1 + sc) for next layer ----
            if (t < HID) {
                int sc = 0;
                float acc = 0.f;
                for (int i = 0; i < lid; i++) {
                    unsigned sk = SI[IO_SKIPS + i];
                    sc += (int)sk;
                    acc += sk ? S[OF_ANCH + i*HID + t] : 0.0f;
                }
                S[OF_XS + t] = __fdividef(acc, 1.0f + (float)sc);
            }
            __syncthreads();
        }
    }

    // ---- final reduction of deferred stats ----
    if (t < 32) {
        float s1 = 0.f, s2 = 0.f, s3 = 0.f;
        for (int i = t; i < 12; i += 32) { s1 += S[OF_BLP + i]; s2 += S[OF_BENT + i]; }
        for (int i = t; i < 66; i += 32) {
            s1 += S[OF_SLP + i]; s2 += S[OF_SENT + i]; s3 += S[OF_SKL + i];
        }
#pragma unroll
        for (int off = 16; off > 0; off >>= 1) {
            s1 += __shfl_down_sync(0xffffffffu, s1, off);
            s2 += __shfl_down_sync(0xffffffffu, s2, off);
            s3 += __shfl_down_sync(0xffffffffu, s3, off);
        }
        if (t == 0) {
            out3[0] = s1;
            out3[1] = s2;
            out3[2] = s3;
        }
    }
}

extern "C" void kernel_launch(void* const* d_in, const int* in_sizes, int n_in,
                              void* d_out, int out_size) {
    const float* g_emb   = (const float*)d_in[0];
    const float* w_emb   = (const float*)d_in[1];
    const float* w_soft  = (const float*)d_in[2];
    const float* w_attn2 = (const float*)d_in[3];
    const float* v_attn  = (const float*)d_in[4];
    const float* w_ih0   = (const float*)d_in[5];
    const float* w_hh0   = (const float*)d_in[6];
    const float* b_ih0   = (const float*)d_in[7];
    const float* b_hh0   = (const float*)d_in[8];
    const float* w_ih1   = (const float*)d_in[9];
    const float* w_hh1   = (const float*)d_in[10];
    const float* b_ih1   = (const float*)d_in[11];
    const float* b_hh1   = (const float*)d_in[12];
    const int*   seed    = (const int*)d_in[13];

    cudaFuncSetAttribute(enas_controller_kernel,
                         cudaFuncAttributeMaxDynamicSharedMemorySize, SMEM_BYTES);
    enas_controller_kernel<<<1, 256, SMEM_BYTES>>>(
        g_emb, w_emb, w_soft, w_attn2, v_attn,
        w_ih0, w_hh0, b_ih0, b_hh0,
        w_ih1, w_hh1, b_ih1, b_hh1,
        seed, (float*)d_out);
}

// round 6
// speedup vs baseline: 5.1448x; 1.1085x over previous
#include <cuda_runtime.h>

// ============================================================================
// EnasController R6: R5 structure with the phase-3 shuffle deadlock fixed
// (full-warp participation) and accurate __expf-based activations restored.
// w_ih1/w_hh0/w_hh1 in registers, 8 barrier phases/layer, deferred stats.
// One persistent block, 256 threads.
// ============================================================================

#define N_LAYERS 12
#define NB 6
#define HID 64
#define PAD 68

typedef unsigned long long u64;

// ---- shared memory layout (float offsets) ----
#define OF_WI0   0                        // 256*68
#define OF_WAT2  (OF_WI0 + 256*PAD)       // 64*68
#define OF_WSOFT (OF_WAT2 + 64*PAD)       // 6*64
#define OF_VATTN (OF_WSOFT + NB*HID)      // 64
#define OF_WEMB  (OF_VATTN + 64)          // 6*64
#define OF_GEMB  (OF_WEMB + NB*HID)       // 64
#define OF_P     (OF_GEMB + 64)           // 7*256
#define OF_XS    (OF_P + 7*256)           // 64
#define OF_H0A   (OF_XS + 64)
#define OF_H0B   (OF_H0A + 64)
#define OF_H1A   (OF_H0B + 64)
#define OF_H1B   (OF_H1A + 64)
#define OF_ANCH  (OF_H1B + 64)            // 12*64
#define OF_AW1   (OF_ANCH + 12*64)        // 12*64
#define OF_W2OUT (OF_AW1 + 12*64)         // 64
#define OF_QVS   (OF_W2OUT + 64)          // 12*16
#define OF_LOGS  (OF_QVS + 12*16)         // 12*8
#define OF_GUMB  (OF_LOGS + 12*8)         // 72
#define OF_GUMS  (OF_GUMB + 72)           // 132
#define OF_BLP   (OF_GUMS + 132)          // 12
#define OF_BENT  (OF_BLP + 12)            // 12
#define OF_SLP   (OF_BENT + 12)           // 66
#define OF_SENT  (OF_SLP + 66)            // 66
#define OF_SKL   (OF_SENT + 66)           // 66
#define OF_IREG  (OF_SKL + 66 + 2)        // uint keys region
#define IO_LKEY  0
#define IO_KB    24
#define IO_KS    48
#define SMEM_FLOATS (OF_IREG + 80)
#define SMEM_BYTES  (SMEM_FLOATS * 4)

#define FMA2(acc, w, x) \
    asm("fma.rn.f32x2 %0, %1, %2, %0;" : "+l"(acc) : "l"(w), "l"(x))

__device__ __forceinline__ float lo32(u64 v) { return __uint_as_float((unsigned)v); }
__device__ __forceinline__ float hi32(u64 v) { return __uint_as_float((unsigned)(v >> 32)); }

__device__ __forceinline__ unsigned rotl32(unsigned x, int r) {
    return (x << r) | (x >> (32 - r));
}

__device__ __forceinline__ void tf2x32(unsigned k0, unsigned k1,
                                       unsigned x0, unsigned x1,
                                       unsigned &o0, unsigned &o1) {
    const unsigned ks2 = k0 ^ k1 ^ 0x1BD11BDAu;
    x0 += k0; x1 += k1;
    x0+=x1; x1=rotl32(x1,13); x1^=x0;
    x0+=x1; x1=rotl32(x1,15); x1^=x0;
    x0+=x1; x1=rotl32(x1,26); x1^=x0;
    x0+=x1; x1=rotl32(x1, 6); x1^=x0;
    x0+=k1; x1+=ks2+1u;
    x0+=x1; x1=rotl32(x1,17); x1^=x0;
    x0+=x1; x1=rotl32(x1,29); x1^=x0;
    x0+=x1; x1=rotl32(x1,16); x1^=x0;
    x0+=x1; x1=rotl32(x1,24); x1^=x0;
    x0+=ks2; x1+=k0+2u;
    x0+=x1; x1=rotl32(x1,13); x1^=x0;
    x0+=x1; x1=rotl32(x1,15); x1^=x0;
    x0+=x1; x1=rotl32(x1,26); x1^=x0;
    x0+=x1; x1=rotl32(x1, 6); x1^=x0;
    x0+=k0; x1+=k1+3u;
    x0+=x1; x1=rotl32(x1,17); x1^=x0;
    x0+=x1; x1=rotl32(x1,29); x1^=x0;
    x0+=x1; x1=rotl32(x1,16); x1^=x0;
    x0+=x1; x1=rotl32(x1,24); x1^=x0;
    x0+=k1; x1+=ks2+4u;
    x0+=x1; x1=rotl32(x1,13); x1^=x0;
    x0+=x1; x1=rotl32(x1,15); x1^=x0;
    x0+=x1; x1=rotl32(x1,26); x1^=x0;
    x0+=x1; x1=rotl32(x1, 6); x1^=x0;
    x0+=ks2; x1+=k0+5u;
    o0 = x0; o1 = x1;
}

__device__ __forceinline__ unsigned rbits32(unsigned k0, unsigned k1, int idx) {
    unsigned o0, o1;
    tf2x32(k0, k1, 0u, (unsigned)idx, o0, o1);
    return o0 ^ o1;
}

__device__ __forceinline__ float gumbel_from_bits(unsigned bits) {
    const float TINY = 1.17549435e-38f;
    float f = __uint_as_float(0x3f800000u | (bits >> 9)) - 1.0f;
    float u = fmaxf(TINY, f + TINY);
    return -logf(-logf(u));
}

// accurate-enough activations (MUFU exp based, err ~1e-7)
__device__ __forceinline__ float fsig(float x) {
    return __fdividef(1.0f, 1.0f + __expf(-x));
}
__device__ __forceinline__ float ftanh(float x) {
    float ax = fabsf(x);
    float e  = __expf(-2.0f * ax);
    float r  = __fdividef(1.0f - e, 1.0f + e);
    return copysignf(r, x);
}

// dot of padded smem row with smem vector (packed f32x2)
__device__ __forceinline__ float dot64p(const ulonglong2* __restrict__ w,
                                        const ulonglong2* __restrict__ v) {
    u64 a0 = 0ull, a1 = 0ull, a2 = 0ull, a3 = 0ull;
#pragma unroll
    for (int k = 0; k < 16; k += 2) {
        ulonglong2 w0 = w[k], w1 = w[k + 1];
        ulonglong2 v0 = v[k], v1 = v[k + 1];
        FMA2(a0, w0.x, v0.x);
        FMA2(a1, w0.y, v0.y);
        FMA2(a2, w1.x, v1.x);
        FMA2(a3, w1.y, v1.y);
    }
    return ((lo32(a0) + hi32(a0)) + (lo32(a1) + hi32(a1)))
         + ((lo32(a2) + hi32(a2)) + (lo32(a3) + hi32(a3)));
}

// dot of register row with smem vector
__device__ __forceinline__ float dot64r(const u64* __restrict__ w,
                                        const ulonglong2* __restrict__ v) {
    u64 a0 = 0ull, a1 = 0ull, a2 = 0ull, a3 = 0ull;
#pragma unroll
    for (int k = 0; k < 16; k += 2) {
        ulonglong2 v0 = v[k], v1 = v[k + 1];
        FMA2(a0, w[2*k],     v0.x);
        FMA2(a1, w[2*k + 1], v0.y);
        FMA2(a2, w[2*k + 2], v1.x);
        FMA2(a3, w[2*k + 3], v1.y);
    }
    return ((lo32(a0) + hi32(a0)) + (lo32(a1) + hi32(a1)))
         + ((lo32(a2) + hi32(a2)) + (lo32(a3) + hi32(a3)));
}

// two register-row dots fused
__device__ __forceinline__ float dot64r2(const u64* __restrict__ wa,
                                         const ulonglong2* __restrict__ va,
                                         const u64* __restrict__ wb,
                                         const ulonglong2* __restrict__ vb) {
    u64 a0 = 0ull, a1 = 0ull, a2 = 0ull, a3 = 0ull;
    u64 b0 = 0ull, b1 = 0ull, b2 = 0ull, b3 = 0ull;
#pragma unroll
    for (int k = 0; k < 16; k += 2) {
        ulonglong2 v0 = va[k], v1 = va[k + 1];
        FMA2(a0, wa[2*k],     v0.x);
        FMA2(a1, wa[2*k + 1], v0.y);
        FMA2(a2, wa[2*k + 2], v1.x);
        FMA2(a3, wa[2*k + 3], v1.y);
        ulonglong2 u0 = vb[k], u1 = vb[k + 1];
        FMA2(b0, wb[2*k],     u0.x);
        FMA2(b1, wb[2*k + 1], u0.y);
        FMA2(b2, wb[2*k + 2], u1.x);
        FMA2(b3, wb[2*k + 3], u1.y);
    }
    float sa = ((lo32(a0) + hi32(a0)) + (lo32(a1) + hi32(a1)))
             + ((lo32(a2) + hi32(a2)) + (lo32(a3) + hi32(a3)));
    float sb = ((lo32(b0) + hi32(b0)) + (lo32(b1) + hi32(b1)))
             + ((lo32(b2) + hi32(b2)) + (lo32(b3) + hi32(b3)));
    return sa + sb;
}

// Epilogue: lane l holds pre-activation for gate (l>>3), row w*8+(l&7).
__device__ __forceinline__ void epi(float acc, float& c,
                                    float* __restrict__ hout,
                                    int l, int rowIdx) {
    int grp = l >> 3, r8 = l & 7;
    float act = (grp == 2) ? ftanh(acc) : fsig(acc);
    float ai = __shfl_sync(0xffffffffu, act, r8);
    float af = __shfl_sync(0xffffffffu, act, r8 + 8);
    float ag = __shfl_sync(0xffffffffu, act, r8 + 16);
    float ao = __shfl_sync(0xffffffffu, act, r8 + 24);
    float cn = af * c + ai * ag;
    c = cn;
    float hv = ao * ftanh(cn);
    if (l < 8) hout[rowIdx] = hv;
    __syncthreads();
}

__global__ __launch_bounds__(256, 1)
void enas_controller_kernel(const float* __restrict__ g_emb,
                            const float* __restrict__ w_emb,
                            const float* __restrict__ w_soft,
                            const float* __restrict__ w_attn2,
                            const float* __restrict__ v_attn,
                            const float* __restrict__ w_ih0,
                            const float* __restrict__ w_hh0,
                            const float* __restrict__ b_ih0,
                            const float* __restrict__ b_hh0,
                            const float* __restrict__ w_ih1,
                            const float* __restrict__ w_hh1,
                            const float* __restrict__ b_ih1,
                            const float* __restrict__ b_hh1,
                            const int* __restrict__ seed_p,
                            float* __restrict__ out3) {
    extern __shared__ __align__(16) float S[];
    unsigned* SI = (unsigned*)&S[OF_IREG];
    const int t = threadIdx.x;
    const int w = t >> 5, l = t & 31;
    const int grp = l >> 3, r8 = l & 7;
    const int rowIdx = w * 8 + r8;
    const int R = grp * 64 + rowIdx;

    // ---- stage weights into smem ----
    {
        const float4* g0 = (const float4*)w_ih0;
        for (int idx = t; idx < 256*16; idx += 256) {
            int row = idx >> 4, col = idx & 15;
            *(float4*)&S[OF_WI0 + row*PAD + col*4] = __ldg(&g0[idx]);
        }
        const float4* ga = (const float4*)w_attn2;
        for (int idx = t; idx < 64*16; idx += 256) {
            int row = idx >> 4, col = idx & 15;
            *(float4*)&S[OF_WAT2 + row*PAD + col*4] = __ldg(&ga[idx]);
        }
        const float4* gs = (const float4*)w_soft;
        if (t < NB*16) *(float4*)&S[OF_WSOFT + t*4] = __ldg(&gs[t]);
        const float4* ge = (const float4*)w_emb;
        if (t >= 32 && t < 32 + NB*16) *(float4*)&S[OF_WEMB + (t-32)*4] = __ldg(&ge[t-32]);
        if (t >= 128 && t < 144) *(float4*)&S[OF_GEMB + (t-128)*4] = __ldg(&((const float4*)g_emb)[t-128]);
        if (t >= 160 && t < 160 + HID) {
            S[OF_VATTN + t - 160] = __ldg(&v_attn[t - 160]);
            S[OF_H0A + t - 160] = 0.f;
            S[OF_H1A + t - 160] = 0.f;
        }
    }

    // ---- register weights: wh0, wh1, wi1 rows for gate row R ----
    u64 wh0[32], wh1[32], wi1[32];
    {
        const ulonglong2* p0 = (const ulonglong2*)(w_hh0 + R*HID);
        const ulonglong2* p1 = (const ulonglong2*)(w_hh1 + R*HID);
        const ulonglong2* p2 = (const ulonglong2*)(w_ih1 + R*HID);
#pragma unroll
        for (int k = 0; k < 16; k++) {
            ulonglong2 v0 = __ldg(&p0[k]);
            ulonglong2 v1 = __ldg(&p1[k]);
            ulonglong2 v2 = __ldg(&p2[k]);
            wh0[2*k] = v0.x; wh0[2*k + 1] = v0.y;
            wh1[2*k] = v1.x; wh1[2*k + 1] = v1.y;
            wi1[2*k] = v2.x; wi1[2*k + 1] = v2.y;
        }
    }
    const float b0R = __ldg(&b_ih0[R]) + __ldg(&b_hh0[R]);
    const float b1R = __ldg(&b_ih1[R]) + __ldg(&b_hh1[R]);

    // ---- RNG: serial key chain, then keys + all gumbels in parallel ----
    if (t == 0) {
        unsigned k0 = 0u, k1 = (unsigned)seed_p[0];
        for (int lid = 0; lid < N_LAYERS; lid++) {
            SI[IO_LKEY + 2*lid]     = k0;
            SI[IO_LKEY + 2*lid + 1] = k1;
            unsigned a0, a1;
            tf2x32(k0, k1, 0u, 0u, a0, a1);
            k0 = a0; k1 = a1;
        }
    }
    __syncthreads();
    if (t < 24) {
        int lid = t >> 1, which = t & 1;
        unsigned o0, o1;
        tf2x32(SI[IO_LKEY + 2*lid], SI[IO_LKEY + 2*lid + 1], 0u, (unsigned)(1 + which), o0, o1);
        int base = which ? IO_KS : IO_KB;
        SI[base + 2*lid] = o0; SI[base + 2*lid + 1] = o1;
    }
    // ---- P table: P[b][R] = bsum0[R] + w_ih0[R,:] . vec_b ----
    {
        const ulonglong2* wrow = (const ulonglong2*)&S[OF_WI0 + R*PAD];
#pragma unroll
        for (int b = 0; b < 7; b++) {
            const ulonglong2* vec = (const ulonglong2*)
                ((b < 6) ? &S[OF_WEMB + b*HID] : &S[OF_GEMB]);
            S[OF_P + b*256 + R] = b0R + dot64p(wrow, vec);
        }
    }
    __syncthreads();
    if (t < 72) {
        int lid = t / NB, j = t % NB;
        S[OF_GUMB + lid*NB + j] =
            gumbel_from_bits(rbits32(SI[IO_KB + 2*lid], SI[IO_KB + 2*lid + 1], j));
    } else if (t < 72 + 132) {
        int f = t - 72;
        int lid = 1;
        while (f >= lid*(lid+1)) lid++;
        int j = f - lid*(lid-1);
        S[OF_GUMS + f] =
            gumbel_from_bits(rbits32(SI[IO_KS + 2*lid], SI[IO_KS + 2*lid + 1], j));
    }
    __syncthreads();

    float c0 = 0.f, c1 = 0.f;

#pragma unroll 1
    for (int lid = 0; lid < N_LAYERS; ++lid) {
        // ===== phase 1: call1-cell0 (reads H0A, writes H0B) =====
        {
            float acc = (lid < 2)
                ? S[OF_P + 6*256 + R]
                : b0R + dot64p((const ulonglong2*)&S[OF_WI0 + R*PAD],
                               (const ulonglong2*)&S[OF_XS]);
            acc += dot64r(wh0, (const ulonglong2*)&S[OF_H0A]);
            epi(acc, c0, &S[OF_H0B], l, rowIdx);
        }
        // ===== phase 2: call1-cell1 (x=H0B, reads H1A, writes H1B) =====
        {
            float acc = b1R + dot64r2(wi1, (const ulonglong2*)&S[OF_H0B],
                                      wh1, (const ulonglong2*)&S[OF_H1A]);
            epi(acc, c1, &S[OF_H1B], l, rowIdx);
        }
        // ===== phase 3: logits = w_soft @ H1B =====
        // 64 threads (2 FULL warps) so width-8 shuffles have every mask lane
        // executing; rows j>=6 are clamped duplicates (benign).
        if (t < 64) {
            int j = t >> 3, k0 = t & 7;
            int jc = (j < NB) ? j : 0;
            const float4* wv = (const float4*)&S[OF_WSOFT + jc*HID + k0*8];
            const float4* hv = (const float4*)&S[OF_H1B + k0*8];
            float4 wa = wv[0], wb = wv[1];
            float4 ha = hv[0], hb = hv[1];
            float s = wa.x*ha.x + wa.y*ha.y + wa.z*ha.z + wa.w*ha.w
                    + wb.x*hb.x + wb.y*hb.y + wb.z*hb.z + wb.w*hb.w;
            s += __shfl_down_sync(0xffffffffu, s, 4, 8);
            s += __shfl_down_sync(0xffffffffu, s, 2, 8);
            s += __shfl_down_sync(0xffffffffu, s, 1, 8);
            if (k0 == 0 && j < NB) S[OF_LOGS + lid*8 + j] = s;
        }
        __syncthreads();

        // ===== phase 4: call2-cell0 (all threads: redundant argmax; P[best]) =====
        {
            float bz = S[OF_LOGS + lid*8] + S[OF_GUMB + lid*NB];
            int best = 0;
#pragma unroll
            for (int j = 1; j < NB; j++) {
                float z = S[OF_LOGS + lid*8 + j] + S[OF_GUMB + lid*NB + j];
                if (z > bz) { bz = z; best = j; }
            }
            float acc = S[OF_P + best*256 + R]
                      + dot64r(wh0, (const ulonglong2*)&S[OF_H0B]);
            epi(acc, c0, &S[OF_H0A], l, rowIdx);
        }
        // ===== phase 5: call2-cell1 (x=H0A, reads H1B, writes H1A) =====
        {
            float acc = b1R + dot64r2(wi1, (const ulonglong2*)&S[OF_H0A],
                                      wh1, (const ulonglong2*)&S[OF_H1B]);
            epi(acc, c1, &S[OF_H1A], l, rowIdx);
        }
        // ===== phase 6: anchor (w2out = wat2 @ H1A) =====
        if (t < HID) {
            float v = dot64p((const ulonglong2*)&S[OF_WAT2 + t*PAD],
                             (const ulonglong2*)&S[OF_H1A]);
            S[OF_W2OUT + t] = v;
            S[OF_AW1 + lid*HID + t] = v;
            S[OF_ANCH + lid*HID + t] = S[OF_H1A + t];
        }
        __syncthreads();

        if (lid > 0) {
            // ===== phase 7: attention q (16 threads/row; warps 0-5 full) =====
            if (t < 192) {
                int r = t >> 4, k0 = t & 15;
                int rc = (r < lid) ? r : 0;
                float s = 0.f;
#pragma unroll
                for (int k = 0; k < 4; k++) {
                    int j = k0 + 16*k;
                    s += ftanh(S[OF_AW1 + rc*HID + j] + S[OF_W2OUT + j]) * S[OF_VATTN + j];
                }
                s += __shfl_down_sync(0xffffffffu, s, 8, 16);
                s += __shfl_down_sync(0xffffffffu, s, 4, 16);
                s += __shfl_down_sync(0xffffffffu, s, 2, 16);
                s += __shfl_down_sync(0xffffffffu, s, 1, 16);
                if (k0 == 0 && r < lid) S[OF_QVS + lid*16 + r] = s;
            }
            __syncthreads();

            // ===== phase 8: xs (redundant skip decisions + anchor average) =====
            if (t < HID) {
                int sc = 0;
                float acc = 0.f;
                for (int i = 0; i < lid; i++) {
                    float l0 = 1.5f * ftanh(S[OF_QVS + lid*16 + i]);
                    float g0 = S[OF_GUMS + lid*(lid-1) + 2*i];
                    float g1 = S[OF_GUMS + lid*(lid-1) + 2*i + 1];
                    int sk = ((-l0) + g1 > l0 + g0) ? 1 : 0;
                    sc += sk;
                    acc += sk ? S[OF_ANCH + i*HID + t] : 0.0f;
                }
                S[OF_XS + t] = __fdividef(acc, 1.0f + (float)sc);
            }
            __syncthreads();
        }
    }

    // ===== deferred stats (once) =====
    if (t < 12) {
        float lv[NB];
#pragma unroll
        for (int j = 0; j < NB; j++) lv[j] = S[OF_LOGS + t*8 + j];
        float m = lv[0];
#pragma unroll
        for (int j = 1; j < NB; j++) m = fmaxf(m, lv[j]);
        float s = 0.f;
#pragma unroll
        for (int j = 0; j < NB; j++) s += __expf(lv[j] - m);
        float lse = __logf(s);
        int best = 0;
        float bz = lv[0] + S[OF_GUMB + t*NB];
#pragma unroll
        for (int j = 1; j < NB; j++) {
            float z = lv[j] + S[OF_GUMB + t*NB + j];
            if (z > bz) { bz = z; best = j; }
        }
        S[OF_BLP + t] = (lv[best] - m) - lse;
        float ent = 0.f;
#pragma unroll
        for (int j = 0; j < NB; j++) {
            float lp = (lv[j] - m) - lse;
            ent -= __expf(lp) * lp;
        }
        S[OF_BENT + t] = ent;
    } else if (t >= 64 && t < 64 + 66) {
        int f = t - 64;                    // slot = lid*(lid-1)/2 + r
        int lid = 1;
        while (f >= (lid*(lid+1)) >> 1) lid++;
        int r = f - ((lid*(lid-1)) >> 1);
        float q = S[OF_QVS + lid*16 + r];
        float l0 = 1.5f * ftanh(q);        // same fn as in-loop decision
        float l1 = -l0;
        float g0 = S[OF_GUMS + lid*(lid-1) + 2*r];
        float g1 = S[OF_GUMS + lid*(lid-1) + 2*r + 1];
        float m = fmaxf(l0, l1);
        float lsr = __logf(__expf(l0 - m) + __expf(l1 - m));
        float lp0 = (l0 - m) - lsr;
        float lp1 = (l1 - m) - lsr;
        S[OF_SLP + f]  = (l1 + g1 > l0 + g0) ? lp1 : lp0;
        S[OF_SENT + f] = -(__expf(lp0)*lp0 + __expf(lp1)*lp1);
        float s0 = __fdividef(1.0f, 1.0f + __expf(-l0));
        float s1 = __fdividef(1.0f, 1.0f + __expf(-l1));
        S[OF_SKL + f] = s0 * __logf(__fdividef(s0, 0.8f))
                      + s1 * __logf(__fdividef(s1, 0.8f));
    }
    __syncthreads();

    if (t < 32) {
        float s1 = 0.f, s2 = 0.f, s3 = 0.f;
        for (int i = t; i < 12; i += 32) { s1 += S[OF_BLP + i]; s2 += S[OF_BENT + i]; }
        for (int i = t; i < 66; i += 32) {
            s1 += S[OF_SLP + i]; s2 += S[OF_SENT + i]; s3 += S[OF_SKL + i];
        }
#pragma unroll
        for (int off = 16; off > 0; off >>= 1) {
            s1 += __shfl_down_sync(0xffffffffu, s1, off);
            s2 += __shfl_down_sync(0xffffffffu, s2, off);
            s3 += __shfl_down_sync(0xffffffffu, s3, off);
        }
        if (t == 0) {
            out3[0] = s1;
            out3[1] = s2;
            out3[2] = s3;
        }
    }
}

extern "C" void kernel_launch(void* const* d_in, const int* in_sizes, int n_in,
                              void* d_out, int out_size) {
    const float* g_emb   = (const float*)d_in[0];
    const float* w_emb   = (const float*)d_in[1];
    const float* w_soft  = (const float*)d_in[2];
    const float* w_attn2 = (const float*)d_in[3];
    const float* v_attn  = (const float*)d_in[4];
    const float* w_ih0   = (const float*)d_in[5];
    const float* w_hh0   = (const float*)d_in[6];
    const float* b_ih0   = (const float*)d_in[7];
    const float* b_hh0   = (const float*)d_in[8];
    const float* w_ih1   = (const float*)d_in[9];
    const float* w_hh1   = (const float*)d_in[10];
    const float* b_ih1   = (const float*)d_in[11];
    const float* b_hh1   = (const float*)d_in[12];
    const int*   seed    = (const int*)d_in[13];

    cudaFuncSetAttribute(enas_controller_kernel,
                         cudaFuncAttributeMaxDynamicSharedMemorySize, SMEM_BYTES);
    enas_controller_kernel<<<1, 256, SMEM_BYTES>>>(
        g_emb, w_emb, w_soft, w_attn2, v_attn,
        w_ih0, w_hh0, b_ih0, b_hh0,
        w_ih1, w_hh1, b_ih1, b_hh1,
        seed, (float*)d_out);
}